// round 12
// baseline (speedup 1.0000x reference)
#include <cuda_runtime.h>
#include <cuda_fp16.h>
#include <cstdint>

#define N_NODES 50000
#define M_PAD   50048
#define N_EDGES 800000
#define IN_FEATS 768
#define HIDDEN 256
#define OUT_FEATS 128
#define SCAN_NBLK ((N_NODES + 255) / 256)   // 196

// layer-2 pipeline split (multiples of 128 rows)
#define HALF0_NODES 25088
#define HALF0_MBLK  (HALF0_NODES / 128)         // 196
#define TOTAL_MBLK  (M_PAD / 128)               // 391
#define HALF1_MBLK  (TOTAL_MBLK - HALF0_MBLK)   // 195

// ------------------------------------------------------------------------
// device scratch
// ------------------------------------------------------------------------
__device__ int   g_cnt[N_NODES];
__device__ int   g_off[N_NODES + 1];
__device__ int   g_cur[N_NODES];
__device__ int   g_csr_src[N_EDGES];
__device__ float g_dinv[N_NODES];
__device__ int   g_bsum[SCAN_NBLK];
__device__ int   g_bpre[SCAN_NBLK];

__device__ __half g_w1h [HIDDEN * IN_FEATS];          // fp16(W1^T)
__device__ __half g_H1h [(size_t)M_PAD * HIDDEN];     // fp16(X @ W1)  pre-agg
__device__ __half g_h1a [(size_t)M_PAD * HIDDEN];     // fp16(relu(agg+b1)); pad rows stay 0
__device__ __half g_w2h [OUT_FEATS * HIDDEN];         // fp16(W2^T)
__device__ __half g_H2h [(size_t)M_PAD * OUT_FEATS];  // fp16(h1a @ W2) pre-agg

// ------------------------------------------------------------------------
// PTX helpers
// ------------------------------------------------------------------------
__device__ __forceinline__ uint32_t smem_u32(const void* p) {
    uint32_t a;
    asm("{ .reg .u64 t; cvta.to.shared.u64 t, %1; cvt.u32.u64 %0, t; }"
        : "=r"(a) : "l"(p));
    return a;
}

__device__ __forceinline__ void cp16(uint32_t dst, const void* src) {
    asm volatile("cp.async.cg.shared.global [%0], [%1], 16;" :: "r"(dst), "l"(src) : "memory");
}

__device__ __forceinline__ void ldsm_x4(uint32_t* r, uint32_t addr) {
    asm volatile("ldmatrix.sync.aligned.m8n8.x4.shared.b16 {%0,%1,%2,%3}, [%4];"
                 : "=r"(r[0]), "=r"(r[1]), "=r"(r[2]), "=r"(r[3]) : "r"(addr));
}

__device__ __forceinline__ void mma_f16(float* d, const uint32_t* a, const uint32_t* b) {
    asm volatile(
        "mma.sync.aligned.m16n8k16.row.col.f32.f16.f16.f32 "
        "{%0,%1,%2,%3}, {%4,%5,%6,%7}, {%8,%9}, {%0,%1,%2,%3};"
        : "+f"(d[0]), "+f"(d[1]), "+f"(d[2]), "+f"(d[3])
        : "r"(a[0]), "r"(a[1]), "r"(a[2]), "r"(a[3]), "r"(b[0]), "r"(b[1]));
}

// convert 8 fp32 -> 8 fp16 and store 16B to smem
__device__ __forceinline__ void cvt_sts16(uint32_t dst, const float4& lo, const float4& hi) {
    __half2 h[4];
    h[0] = __floats2half2_rn(lo.x, lo.y);
    h[1] = __floats2half2_rn(lo.z, lo.w);
    h[2] = __floats2half2_rn(hi.x, hi.y);
    h[3] = __floats2half2_rn(hi.z, hi.w);
    uint4 u = *reinterpret_cast<const uint4*>(h);
    asm volatile("st.shared.v4.b32 [%0], {%1,%2,%3,%4};"
                 :: "r"(dst), "r"(u.x), "r"(u.y), "r"(u.z), "r"(u.w) : "memory");
}

__device__ __forceinline__ void acc8(float* a, const uint4& u, float w) {
    const __half2* h = reinterpret_cast<const __half2*>(&u);
#pragma unroll
    for (int t = 0; t < 4; t++) {
        float2 f = __half22float2(h[t]);
        a[2 * t]     += f.x * w;
        a[2 * t + 1] += f.y * w;
    }
}

__device__ __forceinline__ void acc4(float* a, const uint2& u, float w) {
    const __half2* h = reinterpret_cast<const __half2*>(&u);
#pragma unroll
    for (int t = 0; t < 2; t++) {
        float2 f = __half22float2(h[t]);
        a[2 * t]     += f.x * w;
        a[2 * t + 1] += f.y * w;
    }
}

// ------------------------------------------------------------------------
// CSR build
// ------------------------------------------------------------------------
__global__ void k_zero_cnt() {
    int i = blockIdx.x * blockDim.x + threadIdx.x;
    if (i < N_NODES) g_cnt[i] = 0;
}

__global__ void k_count(const int* __restrict__ dst) {
    int e8 = (blockIdx.x * blockDim.x + threadIdx.x) * 8;
    if (e8 < N_EDGES) {
        int4 d0 = *reinterpret_cast<const int4*>(dst + e8);
        int4 d1 = *reinterpret_cast<const int4*>(dst + e8 + 4);
        atomicAdd(&g_cnt[d0.x], 1); atomicAdd(&g_cnt[d0.y], 1);
        atomicAdd(&g_cnt[d0.z], 1); atomicAdd(&g_cnt[d0.w], 1);
        atomicAdd(&g_cnt[d1.x], 1); atomicAdd(&g_cnt[d1.y], 1);
        atomicAdd(&g_cnt[d1.z], 1); atomicAdd(&g_cnt[d1.w], 1);
    }
}

__global__ void k_bsum() {
    __shared__ int s[256];
    int t = threadIdx.x;
    int i = blockIdx.x * 256 + t;
    int v = (i < N_NODES) ? g_cnt[i] : 0;
    s[t] = v;
    __syncthreads();
    for (int o = 1; o < 256; o <<= 1) {
        int u = (t >= o) ? s[t - o] : 0;
        __syncthreads();
        s[t] += u;
        __syncthreads();
    }
    if (t == 255) g_bsum[blockIdx.x] = s[255];
}

__global__ void k_bscan() {
    __shared__ int s[256];
    int t = threadIdx.x;
    int v = (t < SCAN_NBLK) ? g_bsum[t] : 0;
    s[t] = v;
    __syncthreads();
    for (int o = 1; o < 256; o <<= 1) {
        int u = (t >= o) ? s[t - o] : 0;
        __syncthreads();
        s[t] += u;
        __syncthreads();
    }
    if (t < SCAN_NBLK) g_bpre[t] = s[t] - v;
}

__global__ void k_off() {
    __shared__ int s[256];
    int t = threadIdx.x;
    int i = blockIdx.x * 256 + t;
    int v = (i < N_NODES) ? g_cnt[i] : 0;
    s[t] = v;
    __syncthreads();
    for (int o = 1; o < 256; o <<= 1) {
        int u = (t >= o) ? s[t - o] : 0;
        __syncthreads();
        s[t] += u;
        __syncthreads();
    }
    if (i < N_NODES) {
        int pre = g_bpre[blockIdx.x] + s[t] - v;
        g_off[i] = pre;
        g_cur[i] = pre;
        g_dinv[i] = rsqrtf((float)(v + 1));
    }
    if (i == 0) g_off[N_NODES] = N_EDGES;
}

__global__ void k_fill(const int* __restrict__ src, const int* __restrict__ dst) {
    int e8 = (blockIdx.x * blockDim.x + threadIdx.x) * 8;
    if (e8 < N_EDGES) {
        int4 d0 = *reinterpret_cast<const int4*>(dst + e8);
        int4 d1 = *reinterpret_cast<const int4*>(dst + e8 + 4);
        int4 s0 = *reinterpret_cast<const int4*>(src + e8);
        int4 s1 = *reinterpret_cast<const int4*>(src + e8 + 4);
        g_csr_src[atomicAdd(&g_cur[d0.x], 1)] = s0.x;
        g_csr_src[atomicAdd(&g_cur[d0.y], 1)] = s0.y;
        g_csr_src[atomicAdd(&g_cur[d0.z], 1)] = s0.z;
        g_csr_src[atomicAdd(&g_cur[d0.w], 1)] = s0.w;
        g_csr_src[atomicAdd(&g_cur[d1.x], 1)] = s1.x;
        g_csr_src[atomicAdd(&g_cur[d1.y], 1)] = s1.y;
        g_csr_src[atomicAdd(&g_cur[d1.z], 1)] = s1.z;
        g_csr_src[atomicAdd(&g_cur[d1.w], 1)] = s1.w;
    }
}

// transpose weights to fp16: W[K][N] -> Wt[N][K]
__global__ void k_wT(const float* __restrict__ W, int K, int N,
                     __half* __restrict__ out) {
    int idx = blockIdx.x * blockDim.x + threadIdx.x;
    if (idx >= N * K) return;
    int n = idx / K, k = idx % K;
    out[idx] = __float2half_rn(W[(size_t)k * N + n]);
}

// ------------------------------------------------------------------------
// GEMM constants
// ------------------------------------------------------------------------
static constexpr int ROWB   = 80;
static constexpr int TILEB  = 128 * ROWB;            // 10240 (128-row tile)
static constexpr int TILEA1 = 64 * ROWB;             // 5120  (64-row A tile, GEMM1)
static constexpr int TILEB2 = 256 * ROWB;            // 20480 (256-row B tile, GEMM1)

// ==========================================================================
// GEMM1: C[M,256] = fp16(A_fp32) * B^T, CTA tile 64x256.
// A converted on the fly (1 chunk/thread, double buffer); B 4-stage cp.async.
// smem = 2*TILEA1 + 4*TILEB2 = 92160; 2 CTA/SM.
// ==========================================================================
static constexpr int SMEMB1 = 2 * TILEA1 + 4 * TILEB2;   // 92160

template <int KTOT>
__device__ __forceinline__ void load_B1(
    uint32_t sbB, int tid, int kc, const __half* __restrict__ B)
{
    const int k0 = kc * 32;
#pragma unroll
    for (int j = 0; j < 4; j++) {                   // 256 rows * 4 chunks / 256 thr
        int linear = j * 256 + tid;
        int row    = linear >> 2;
        int chunk  = linear & 3;
        cp16(sbB + row * ROWB + chunk * 16,
             B + (size_t)row * KTOT + k0 + chunk * 8);
    }
    asm volatile("cp.async.commit_group;" ::: "memory");
}

template <int KTOT>
__global__ __launch_bounds__(256, 2) void k_mma_xA(
    const float* __restrict__ A,        // fp32 [N_NODES, KTOT]
    const __half* __restrict__ B,       // fp16 [256, KTOT]
    __half* __restrict__ C, int ldc)
{
    constexpr int NC = KTOT / 32;
    extern __shared__ __align__(128) char smem[];
    const uint32_t sb0 = smem_u32(smem);            // A bufs at 0, TILEA1
    const uint32_t sbB0 = sb0 + 2 * TILEA1;         // B stages
    const int tid  = threadIdx.x;
    const int lane = tid & 31;
    const int wid  = tid >> 5;
    const int wm   = wid & 1;        // 2 warps down M (32 rows)
    const int wn   = wid >> 1;       // 4 warps across N (64 cols)
    const int m0 = blockIdx.x * 64;

    // one A chunk (16B fp16 = 8 source fp32) per thread
    const int ar = tid >> 2, ac = tid & 3;
    const bool av = (m0 + ar) < N_NODES;
    const float* ap = A + (size_t)(m0 + ar) * KTOT + ac * 8;
    const uint32_t ao = ar * ROWB + ac * 16;

    float acc[2][8][4];
#pragma unroll
    for (int i = 0; i < 2; i++)
#pragma unroll
        for (int j = 0; j < 8; j++)
#pragma unroll
            for (int q = 0; q < 4; q++) acc[i][j][q] = 0.f;

    const int g = lane >> 3;
    const int r = lane & 7;
    const float4 z4 = make_float4(0.f, 0.f, 0.f, 0.f);

    load_B1<KTOT>(sbB0, tid, 0, B);
    if (NC > 1) load_B1<KTOT>(sbB0 + TILEB2, tid, 1, B);
    if (NC > 2) load_B1<KTOT>(sbB0 + 2 * TILEB2, tid, 2, B);
    {
        float4 pa = av ? *reinterpret_cast<const float4*>(ap)     : z4;
        float4 pb = av ? *reinterpret_cast<const float4*>(ap + 4) : z4;
        cvt_sts16(sb0 + ao, pa, pb);
    }

    for (int c = 0; c < NC; c++) {
        const int rem = NC - 1 - c;
        if (rem >= 2)      asm volatile("cp.async.wait_group 2;" ::: "memory");
        else if (rem == 1) asm volatile("cp.async.wait_group 1;" ::: "memory");
        else               asm volatile("cp.async.wait_group 0;" ::: "memory");
        __syncthreads();

        float4 pa = z4, pb = z4;
        if (c + 1 < NC) {
            const int k0n = (c + 1) * 32;
            if (av) {
                pa = *reinterpret_cast<const float4*>(ap + k0n);
                pb = *reinterpret_cast<const float4*>(ap + k0n + 4);
            }
        }
        if (c + 3 < NC)
            load_B1<KTOT>(sbB0 + ((c + 3) & 3) * TILEB2, tid, c + 3, B);

        const uint32_t sbA = sb0 + (c & 1) * TILEA1;
        const uint32_t sbB = sbB0 + (c & 3) * TILEB2;
#pragma unroll
        for (int kk = 0; kk < 2; kk++) {
            uint32_t af[2][4];
#pragma unroll
            for (int ms = 0; ms < 2; ms++) {
                uint32_t arow = wm * 32 + ms * 16 + ((g & 1) << 3) + r;
                uint32_t aoff = arow * ROWB + kk * 32 + ((g >> 1) << 4);
                ldsm_x4(af[ms], sbA + aoff);
            }
#pragma unroll
            for (int nb2 = 0; nb2 < 4; nb2++) {
                uint32_t nrow = wn * 64 + nb2 * 16 + ((g >> 1) << 3) + r;
                uint32_t boff = nrow * ROWB + kk * 32 + ((g & 1) << 4);
                uint32_t bf[4];
                ldsm_x4(bf, sbB + boff);
#pragma unroll
                for (int ms = 0; ms < 2; ms++)
#pragma unroll
                    for (int h = 0; h < 2; h++)
                        mma_f16(acc[ms][nb2 * 2 + h], af[ms], &bf[h * 2]);
            }
        }

        if (c + 1 < NC) {
            const uint32_t sbAn = sb0 + ((c + 1) & 1) * TILEA1;
            cvt_sts16(sbAn + ao, pa, pb);
        }
    }

#pragma unroll
    for (int ms = 0; ms < 2; ms++) {
        int grow = m0 + wm * 32 + ms * 16 + (lane >> 2);
#pragma unroll
        for (int nb = 0; nb < 8; nb++) {
            int gcol = wn * 64 + nb * 8 + (lane & 3) * 2;
            *reinterpret_cast<__half2*>(&C[(size_t)grow * ldc + gcol]) =
                __floats2half2_rn(acc[ms][nb][0], acc[ms][nb][1]);
            *reinterpret_cast<__half2*>(&C[(size_t)(grow + 8) * ldc + gcol]) =
                __floats2half2_rn(acc[ms][nb][2], acc[ms][nb][3]);
        }
    }
}

// ==========================================================================
// GEMM2: fp16 A and B via 4-stage cp.async (CTA 128x128, mbase for M split)
// ==========================================================================
static constexpr int STAGEB = 2 * TILEB;
static constexpr int NSTAGE = 4;
static constexpr int SMEMB2 = NSTAGE * STAGEB;      // 81920

template <int KTOT>
__device__ __forceinline__ void load_stage(
    uint32_t sb, int tid, int kc, int m0, int n0,
    const __half* __restrict__ A, const __half* __restrict__ B)
{
    const int k0 = kc * 32;
#pragma unroll
    for (int j = 0; j < 4; j++) {
        int linear = j * 256 + tid;
        int tile   = linear >> 9;
        int within = linear & 511;
        int row    = within >> 2;
        int chunk  = within & 3;
        const __half* base = (tile == 0) ? A : B;
        int grow = ((tile == 0) ? m0 : n0) + row;
        const void* g = base + (size_t)grow * KTOT + k0 + chunk * 8;
        cp16(sb + tile * TILEB + row * ROWB + chunk * 16, g);
    }
    asm volatile("cp.async.commit_group;" ::: "memory");
}

template <int KTOT>
__global__ __launch_bounds__(256, 2) void k_mma(
    const __half* __restrict__ A, const __half* __restrict__ B,
    __half* __restrict__ C, int ldc, int mbase)
{
    constexpr int NC = KTOT / 32;
    extern __shared__ __align__(128) char smem[];
    const uint32_t sb0 = smem_u32(smem);
    const int tid  = threadIdx.x;
    const int lane = tid & 31;
    const int wid  = tid >> 5;
    const int wm   = wid & 3;
    const int wn   = wid >> 2;
    const int m0 = (mbase + blockIdx.y) * 128, n0 = blockIdx.x * 128;

    float acc[2][8][4];
#pragma unroll
    for (int i = 0; i < 2; i++)
#pragma unroll
        for (int j = 0; j < 8; j++)
#pragma unroll
            for (int q = 0; q < 4; q++) acc[i][j][q] = 0.f;

    const int g = lane >> 3;
    const int r = lane & 7;

    load_stage<KTOT>(sb0, tid, 0, m0, n0, A, B);
    if (NC > 1) load_stage<KTOT>(sb0 + STAGEB, tid, 1, m0, n0, A, B);
    if (NC > 2) load_stage<KTOT>(sb0 + 2 * STAGEB, tid, 2, m0, n0, A, B);

    for (int c = 0; c < NC; c++) {
        const int rem = NC - 1 - c;
        if (rem >= 2)      asm volatile("cp.async.wait_group 2;" ::: "memory");
        else if (rem == 1) asm volatile("cp.async.wait_group 1;" ::: "memory");
        else               asm volatile("cp.async.wait_group 0;" ::: "memory");
        __syncthreads();

        if (c + 3 < NC)
            load_stage<KTOT>(sb0 + ((c + 3) % NSTAGE) * STAGEB, tid, c + 3,
                             m0, n0, A, B);

        const uint32_t sb = sb0 + (c % NSTAGE) * STAGEB;
#pragma unroll
        for (int kk = 0; kk < 2; kk++) {
            uint32_t af[2][4];
#pragma unroll
            for (int ms = 0; ms < 2; ms++) {
                uint32_t arow = wm * 32 + ms * 16 + ((g & 1) << 3) + r;
                uint32_t aoff = arow * ROWB + kk * 32 + ((g >> 1) << 4);
                ldsm_x4(af[ms], sb + aoff);
            }
#pragma unroll
            for (int nb2 = 0; nb2 < 4; nb2++) {
                uint32_t nrow = wn * 64 + nb2 * 16 + ((g >> 1) << 3) + r;
                uint32_t boff = nrow * ROWB + kk * 32 + ((g & 1) << 4);
                uint32_t bf[4];
                ldsm_x4(bf, sb + TILEB + boff);
#pragma unroll
                for (int ms = 0; ms < 2; ms++)
#pragma unroll
                    for (int h = 0; h < 2; h++)
                        mma_f16(acc[ms][nb2 * 2 + h], af[ms], &bf[h * 2]);
            }
        }
        __syncthreads();
    }

#pragma unroll
    for (int ms = 0; ms < 2; ms++) {
        int grow = m0 + wm * 32 + ms * 16 + (lane >> 2);
#pragma unroll
        for (int nb = 0; nb < 8; nb++) {
            int gcol = n0 + wn * 64 + nb * 8 + (lane & 3) * 2;
            *reinterpret_cast<__half2*>(&C[(size_t)grow * ldc + gcol]) =
                __floats2half2_rn(acc[ms][nb][0], acc[ms][nb][1]);
            *reinterpret_cast<__half2*>(&C[(size_t)(grow + 8) * ldc + gcol]) =
                __floats2half2_rn(acc[ms][nb][2], acc[ms][nb][3]);
        }
    }
}

// ------------------------------------------------------------------------
// aggregation: warp-per-node fp16 gather, fp32 accumulate
// k_agg1 takes a node range [node_base, node_end) for layer-2 pipelining
// ------------------------------------------------------------------------
__global__ __launch_bounds__(256) void k_agg1(const float* __restrict__ b1,
                                              int node_base, int node_end) {
    int node = node_base + blockIdx.x * 8 + (threadIdx.x >> 5);
    if (node >= node_end) return;
    int lane = threadIdx.x & 31;
    float wd = g_dinv[node];

    float a[8];
    {
        uint4 u = *reinterpret_cast<const uint4*>(&g_H1h[(size_t)node * HIDDEN + lane * 8]);
        const __half2* h = reinterpret_cast<const __half2*>(&u);
        float sw = wd * wd;
#pragma unroll
        for (int t = 0; t < 4; t++) {
            float2 f = __half22float2(h[t]);
            a[2 * t]     = f.x * sw;
            a[2 * t + 1] = f.y * sw;
        }
    }

    int beg = g_off[node], end = g_off[node + 1];
    int i = beg;
    for (; i + 3 < end; i += 4) {
        int s0 = g_csr_src[i];
        int s1 = g_csr_src[i + 1];
        int s2 = g_csr_src[i + 2];
        int s3 = g_csr_src[i + 3];
        uint4 u0 = *reinterpret_cast<const uint4*>(&g_H1h[(size_t)s0 * HIDDEN + lane * 8]);
        uint4 u1 = *reinterpret_cast<const uint4*>(&g_H1h[(size_t)s1 * HIDDEN + lane * 8]);
        uint4 u2 = *reinterpret_cast<const uint4*>(&g_H1h[(size_t)s2 * HIDDEN + lane * 8]);
        uint4 u3 = *reinterpret_cast<const uint4*>(&g_H1h[(size_t)s3 * HIDDEN + lane * 8]);
        float w0 = g_dinv[s0] * wd;
        float w1 = g_dinv[s1] * wd;
        float w2 = g_dinv[s2] * wd;
        float w3 = g_dinv[s3] * wd;
        acc8(a, u0, w0);
        acc8(a, u1, w1);
        acc8(a, u2, w2);
        acc8(a, u3, w3);
    }
    for (; i < end; i++) {
        int s0 = g_csr_src[i];
        float w0 = g_dinv[s0] * wd;
        uint4 u0 = *reinterpret_cast<const uint4*>(&g_H1h[(size_t)s0 * HIDDEN + lane * 8]);
        acc8(a, u0, w0);
    }

    float4 bb0 = *reinterpret_cast<const float4*>(&b1[lane * 8]);
    float4 bb1 = *reinterpret_cast<const float4*>(&b1[lane * 8 + 4]);
    float rr[8];
    rr[0] = fmaxf(a[0] + bb0.x, 0.f); rr[1] = fmaxf(a[1] + bb0.y, 0.f);
    rr[2] = fmaxf(a[2] + bb0.z, 0.f); rr[3] = fmaxf(a[3] + bb0.w, 0.f);
    rr[4] = fmaxf(a[4] + bb1.x, 0.f); rr[5] = fmaxf(a[5] + bb1.y, 0.f);
    rr[6] = fmaxf(a[6] + bb1.z, 0.f); rr[7] = fmaxf(a[7] + bb1.w, 0.f);

    __half2 o[4];
#pragma unroll
    for (int t = 0; t < 4; t++) o[t] = __floats2half2_rn(rr[2 * t], rr[2 * t + 1]);
    *reinterpret_cast<uint4*>(&g_h1a[(size_t)node * HIDDEN + lane * 8]) =
        *reinterpret_cast<const uint4*>(o);
}

__global__ __launch_bounds__(256) void k_agg2(const float* __restrict__ b2,
                                              float* __restrict__ out) {
    int node = blockIdx.x * 8 + (threadIdx.x >> 5);
    if (node >= N_NODES) return;
    int lane = threadIdx.x & 31;
    float wd = g_dinv[node];

    float a[4];
    {
        uint2 u = *reinterpret_cast<const uint2*>(&g_H2h[(size_t)node * OUT_FEATS + lane * 4]);
        const __half2* h = reinterpret_cast<const __half2*>(&u);
        float sw = wd * wd;
#pragma unroll
        for (int t = 0; t < 2; t++) {
            float2 f = __half22float2(h[t]);
            a[2 * t]     = f.x * sw;
            a[2 * t + 1] = f.y * sw;
        }
    }

    int beg = g_off[node], end = g_off[node + 1];
    int i = beg;
    for (; i + 3 < end; i += 4) {
        int s0 = g_csr_src[i];
        int s1 = g_csr_src[i + 1];
        int s2 = g_csr_src[i + 2];
        int s3 = g_csr_src[i + 3];
        uint2 u0 = *reinterpret_cast<const uint2*>(&g_H2h[(size_t)s0 * OUT_FEATS + lane * 4]);
        uint2 u1 = *reinterpret_cast<const uint2*>(&g_H2h[(size_t)s1 * OUT_FEATS + lane * 4]);
        uint2 u2 = *reinterpret_cast<const uint2*>(&g_H2h[(size_t)s2 * OUT_FEATS + lane * 4]);
        uint2 u3 = *reinterpret_cast<const uint2*>(&g_H2h[(size_t)s3 * OUT_FEATS + lane * 4]);
        float w0 = g_dinv[s0] * wd;
        float w1 = g_dinv[s1] * wd;
        float w2 = g_dinv[s2] * wd;
        float w3 = g_dinv[s3] * wd;
        acc4(a, u0, w0);
        acc4(a, u1, w1);
        acc4(a, u2, w2);
        acc4(a, u3, w3);
    }
    for (; i < end; i++) {
        int s0 = g_csr_src[i];
        float w0 = g_dinv[s0] * wd;
        uint2 u0 = *reinterpret_cast<const uint2*>(&g_H2h[(size_t)s0 * OUT_FEATS + lane * 4]);
        acc4(a, u0, w0);
    }

    float4 bb = *reinterpret_cast<const float4*>(&b2[lane * 4]);
    *reinterpret_cast<float4*>(&out[(size_t)node * OUT_FEATS + lane * 4]) =
        make_float4(a[0] + bb.x, a[1] + bb.y, a[2] + bb.z, a[3] + bb.w);
}

// ------------------------------------------------------------------------
// launch
// ------------------------------------------------------------------------
extern "C" void kernel_launch(void* const* d_in, const int* in_sizes, int n_in,
                              void* d_out, int out_size) {
    const float* x  = (const float*)d_in[0];
    const int*   ei = (const int*)d_in[1];
    const float* W1 = (const float*)d_in[2];
    const float* b1 = (const float*)d_in[3];
    const float* W2 = (const float*)d_in[4];
    const float* b2 = (const float*)d_in[5];
    float* out = (float*)d_out;

    const int* src = ei;
    const int* dst = ei + N_EDGES;

    __half *w1h, *H1h, *h1a, *w2h, *H2h;
    cudaGetSymbolAddress((void**)&w1h, g_w1h);
    cudaGetSymbolAddress((void**)&H1h, g_H1h);
    cudaGetSymbolAddress((void**)&h1a, g_h1a);
    cudaGetSymbolAddress((void**)&w2h, g_w2h);
    cudaGetSymbolAddress((void**)&H2h, g_H2h);

    static cudaStream_t s_side = nullptr;
    static cudaEvent_t ev_fork = nullptr, ev_csr = nullptr, ev_h0 = nullptr, ev_g2h0 = nullptr;
    if (s_side == nullptr) {
        cudaStreamCreateWithFlags(&s_side, cudaStreamNonBlocking);
        cudaEventCreateWithFlags(&ev_fork, cudaEventDisableTiming);
        cudaEventCreateWithFlags(&ev_csr,  cudaEventDisableTiming);
        cudaEventCreateWithFlags(&ev_h0,   cudaEventDisableTiming);
        cudaEventCreateWithFlags(&ev_g2h0, cudaEventDisableTiming);
        cudaFuncSetAttribute(k_mma_xA<IN_FEATS>, cudaFuncAttributeMaxDynamicSharedMemorySize, SMEMB1);
        cudaFuncSetAttribute(k_mma<HIDDEN>,      cudaFuncAttributeMaxDynamicSharedMemorySize, SMEMB2);
    }

    // fork
    cudaEventRecord(ev_fork, 0);
    cudaStreamWaitEvent(s_side, ev_fork, 0);

    // side: CSR build + W2 transpose
    k_zero_cnt<<<(N_NODES + 255) / 256, 256, 0, s_side>>>();
    k_count<<<(N_EDGES / 8 + 255) / 256, 256, 0, s_side>>>(dst);
    k_bsum<<<SCAN_NBLK, 256, 0, s_side>>>();
    k_bscan<<<1, 256, 0, s_side>>>();
    k_off<<<SCAN_NBLK, 256, 0, s_side>>>();
    k_fill<<<(N_EDGES / 8 + 255) / 256, 256, 0, s_side>>>(src, dst);
    k_wT<<<(OUT_FEATS * HIDDEN + 255) / 256, 256, 0, s_side>>>(W2, HIDDEN, OUT_FEATS, w2h);
    cudaEventRecord(ev_csr, s_side);

    // main: W1 transpose, fused-convert GEMM1 (64x256 tiles)
    k_wT<<<(HIDDEN * IN_FEATS + 255) / 256, 256>>>(W1, IN_FEATS, HIDDEN, w1h);
    k_mma_xA<IN_FEATS><<<M_PAD / 64, 256, SMEMB1>>>(x, w1h, H1h, HIDDEN);

    // join CSR; agg1 half 0
    cudaStreamWaitEvent(0, ev_csr, 0);
    k_agg1<<<HALF0_NODES / 8, 256>>>(b1, 0, HALF0_NODES);
    cudaEventRecord(ev_h0, 0);

    // side: GEMM2 on rows [0, HALF0_NODES) while main does agg1 half 1
    cudaStreamWaitEvent(s_side, ev_h0, 0);
    k_mma<HIDDEN><<<dim3(OUT_FEATS / 128, HALF0_MBLK), 256, SMEMB2, s_side>>>(
        h1a, w2h, H2h, OUT_FEATS, 0);
    cudaEventRecord(ev_g2h0, s_side);

    // main: agg1 half 1, then GEMM2 on remaining rows
    k_agg1<<<(N_NODES - HALF0_NODES + 7) / 8, 256>>>(b1, HALF0_NODES, N_NODES);
    k_mma<HIDDEN><<<dim3(OUT_FEATS / 128, HALF1_MBLK), 256, SMEMB2>>>(
        h1a, w2h, H2h, OUT_FEATS, HALF0_MBLK);

    // join: agg2 needs full H2h
    cudaStreamWaitEvent(0, ev_g2h0, 0);
    k_agg2<<<(N_NODES + 7) / 8, 256>>>(b2, out);
}

// round 13
// speedup vs baseline: 1.0203x; 1.0203x over previous
#include <cuda_runtime.h>
#include <cuda_fp16.h>
#include <cstdint>

#define N_NODES 50000
#define M_PAD   50048
#define N_EDGES 800000
#define IN_FEATS 768
#define HIDDEN 256
#define OUT_FEATS 128
#define SCAN_NBLK ((N_NODES + 255) / 256)   // 196

// layer-2 pipeline split (multiples of 128 rows)
#define HALF0_NODES 25088
#define HALF0_MBLK  (HALF0_NODES / 128)         // 196
#define TOTAL_MBLK  (M_PAD / 128)               // 391
#define HALF1_MBLK  (TOTAL_MBLK - HALF0_MBLK)   // 195

// ------------------------------------------------------------------------
// device scratch
// ------------------------------------------------------------------------
__device__ int   g_cnt[N_NODES];
__device__ int   g_off[N_NODES + 1];
__device__ int   g_cur[N_NODES];
__device__ int   g_csr_src[N_EDGES];
__device__ float g_dinv[N_NODES];
__device__ int   g_bsum[SCAN_NBLK];
__device__ int   g_bpre[SCAN_NBLK];

__device__ __half g_w1h [HIDDEN * IN_FEATS];          // fp16(W1^T)
__device__ __half g_H1h [(size_t)M_PAD * HIDDEN];     // fp16(X @ W1)  pre-agg
__device__ __half g_h1a [(size_t)M_PAD * HIDDEN];     // fp16(relu(agg+b1)); pad rows stay 0
__device__ __half g_w2h [OUT_FEATS * HIDDEN];         // fp16(W2^T)
__device__ __half g_H2h [(size_t)M_PAD * OUT_FEATS];  // fp16(h1a @ W2) pre-agg

// ------------------------------------------------------------------------
// PTX helpers
// ------------------------------------------------------------------------
__device__ __forceinline__ uint32_t smem_u32(const void* p) {
    uint32_t a;
    asm("{ .reg .u64 t; cvta.to.shared.u64 t, %1; cvt.u32.u64 %0, t; }"
        : "=r"(a) : "l"(p));
    return a;
}

__device__ __forceinline__ void cp16(uint32_t dst, const void* src) {
    asm volatile("cp.async.cg.shared.global [%0], [%1], 16;" :: "r"(dst), "l"(src) : "memory");
}

__device__ __forceinline__ void ldsm_x4(uint32_t* r, uint32_t addr) {
    asm volatile("ldmatrix.sync.aligned.m8n8.x4.shared.b16 {%0,%1,%2,%3}, [%4];"
                 : "=r"(r[0]), "=r"(r[1]), "=r"(r[2]), "=r"(r[3]) : "r"(addr));
}

__device__ __forceinline__ void mma_f16(float* d, const uint32_t* a, const uint32_t* b) {
    asm volatile(
        "mma.sync.aligned.m16n8k16.row.col.f32.f16.f16.f32 "
        "{%0,%1,%2,%3}, {%4,%5,%6,%7}, {%8,%9}, {%0,%1,%2,%3};"
        : "+f"(d[0]), "+f"(d[1]), "+f"(d[2]), "+f"(d[3])
        : "r"(a[0]), "r"(a[1]), "r"(a[2]), "r"(a[3]), "r"(b[0]), "r"(b[1]));
}

// convert 8 fp32 -> 8 fp16 and store 16B to smem
__device__ __forceinline__ void cvt_sts16(uint32_t dst, const float4& lo, const float4& hi) {
    __half2 h[4];
    h[0] = __floats2half2_rn(lo.x, lo.y);
    h[1] = __floats2half2_rn(lo.z, lo.w);
    h[2] = __floats2half2_rn(hi.x, hi.y);
    h[3] = __floats2half2_rn(hi.z, hi.w);
    uint4 u = *reinterpret_cast<const uint4*>(h);
    asm volatile("st.shared.v4.b32 [%0], {%1,%2,%3,%4};"
                 :: "r"(dst), "r"(u.x), "r"(u.y), "r"(u.z), "r"(u.w) : "memory");
}

__device__ __forceinline__ void acc8(float* a, const uint4& u, float w) {
    const __half2* h = reinterpret_cast<const __half2*>(&u);
#pragma unroll
    for (int t = 0; t < 4; t++) {
        float2 f = __half22float2(h[t]);
        a[2 * t]     += f.x * w;
        a[2 * t + 1] += f.y * w;
    }
}

__device__ __forceinline__ void acc4(float* a, const uint2& u, float w) {
    const __half2* h = reinterpret_cast<const __half2*>(&u);
#pragma unroll
    for (int t = 0; t < 2; t++) {
        float2 f = __half22float2(h[t]);
        a[2 * t]     += f.x * w;
        a[2 * t + 1] += f.y * w;
    }
}

// ------------------------------------------------------------------------
// CSR build
// ------------------------------------------------------------------------
__global__ void k_zero_cnt() {
    int i = blockIdx.x * blockDim.x + threadIdx.x;
    if (i < N_NODES) g_cnt[i] = 0;
}

__global__ void k_count(const int* __restrict__ dst) {
    int e8 = (blockIdx.x * blockDim.x + threadIdx.x) * 8;
    if (e8 < N_EDGES) {
        int4 d0 = *reinterpret_cast<const int4*>(dst + e8);
        int4 d1 = *reinterpret_cast<const int4*>(dst + e8 + 4);
        atomicAdd(&g_cnt[d0.x], 1); atomicAdd(&g_cnt[d0.y], 1);
        atomicAdd(&g_cnt[d0.z], 1); atomicAdd(&g_cnt[d0.w], 1);
        atomicAdd(&g_cnt[d1.x], 1); atomicAdd(&g_cnt[d1.y], 1);
        atomicAdd(&g_cnt[d1.z], 1); atomicAdd(&g_cnt[d1.w], 1);
    }
}

__global__ void k_bsum() {
    __shared__ int s[256];
    int t = threadIdx.x;
    int i = blockIdx.x * 256 + t;
    int v = (i < N_NODES) ? g_cnt[i] : 0;
    s[t] = v;
    __syncthreads();
    for (int o = 1; o < 256; o <<= 1) {
        int u = (t >= o) ? s[t - o] : 0;
        __syncthreads();
        s[t] += u;
        __syncthreads();
    }
    if (t == 255) g_bsum[blockIdx.x] = s[255];
}

__global__ void k_bscan() {
    __shared__ int s[256];
    int t = threadIdx.x;
    int v = (t < SCAN_NBLK) ? g_bsum[t] : 0;
    s[t] = v;
    __syncthreads();
    for (int o = 1; o < 256; o <<= 1) {
        int u = (t >= o) ? s[t - o] : 0;
        __syncthreads();
        s[t] += u;
        __syncthreads();
    }
    if (t < SCAN_NBLK) g_bpre[t] = s[t] - v;
}

__global__ void k_off() {
    __shared__ int s[256];
    int t = threadIdx.x;
    int i = blockIdx.x * 256 + t;
    int v = (i < N_NODES) ? g_cnt[i] : 0;
    s[t] = v;
    __syncthreads();
    for (int o = 1; o < 256; o <<= 1) {
        int u = (t >= o) ? s[t - o] : 0;
        __syncthreads();
        s[t] += u;
        __syncthreads();
    }
    if (i < N_NODES) {
        int pre = g_bpre[blockIdx.x] + s[t] - v;
        g_off[i] = pre;
        g_cur[i] = pre;
        g_dinv[i] = rsqrtf((float)(v + 1));
    }
    if (i == 0) g_off[N_NODES] = N_EDGES;
}

__global__ void k_fill(const int* __restrict__ src, const int* __restrict__ dst) {
    int e8 = (blockIdx.x * blockDim.x + threadIdx.x) * 8;
    if (e8 < N_EDGES) {
        int4 d0 = *reinterpret_cast<const int4*>(dst + e8);
        int4 d1 = *reinterpret_cast<const int4*>(dst + e8 + 4);
        int4 s0 = *reinterpret_cast<const int4*>(src + e8);
        int4 s1 = *reinterpret_cast<const int4*>(src + e8 + 4);
        g_csr_src[atomicAdd(&g_cur[d0.x], 1)] = s0.x;
        g_csr_src[atomicAdd(&g_cur[d0.y], 1)] = s0.y;
        g_csr_src[atomicAdd(&g_cur[d0.z], 1)] = s0.z;
        g_csr_src[atomicAdd(&g_cur[d0.w], 1)] = s0.w;
        g_csr_src[atomicAdd(&g_cur[d1.x], 1)] = s1.x;
        g_csr_src[atomicAdd(&g_cur[d1.y], 1)] = s1.y;
        g_csr_src[atomicAdd(&g_cur[d1.z], 1)] = s1.z;
        g_csr_src[atomicAdd(&g_cur[d1.w], 1)] = s1.w;
    }
}

// transpose weights to fp16: W[K][N] -> Wt[N][K]
__global__ void k_wT(const float* __restrict__ W, int K, int N,
                     __half* __restrict__ out) {
    int idx = blockIdx.x * blockDim.x + threadIdx.x;
    if (idx >= N * K) return;
    int n = idx / K, k = idx % K;
    out[idx] = __float2half_rn(W[(size_t)k * N + n]);
}

// ------------------------------------------------------------------------
// GEMM constants
// ------------------------------------------------------------------------
static constexpr int ROWB   = 80;
static constexpr int TILEB  = 128 * ROWB;            // 10240 (128-row tile)
static constexpr int TILEB2 = 256 * ROWB;            // 20480 (256-row tile)

// ==========================================================================
// GEMM1 (R11 config): C[M,256] = fp16(A_fp32) * B^T, CTA tile 128x256.
// A converted on the fly (register-staged double buffer); B 4-stage cp.async.
// smem = 2*TILEB + 4*TILEB2 = 102400.  1 CTA/SM.
// ==========================================================================
static constexpr int SMEMB1 = 2 * TILEB + 4 * TILEB2;   // 102400

template <int KTOT>
__device__ __forceinline__ void load_B1(
    uint32_t sbB, int tid, int kc, const __half* __restrict__ B)
{
    const int k0 = kc * 32;
#pragma unroll
    for (int j = 0; j < 4; j++) {                   // 256 rows * 4 chunks / 256 thr
        int linear = j * 256 + tid;
        int row    = linear >> 2;
        int chunk  = linear & 3;
        cp16(sbB + row * ROWB + chunk * 16,
             B + (size_t)row * KTOT + k0 + chunk * 8);
    }
    asm volatile("cp.async.commit_group;" ::: "memory");
}

template <int KTOT>
__global__ __launch_bounds__(256, 1) void k_mma_xA(
    const float* __restrict__ A,        // fp32 [N_NODES, KTOT]
    const __half* __restrict__ B,       // fp16 [256, KTOT]
    __half* __restrict__ C, int ldc)
{
    constexpr int NC = KTOT / 32;
    extern __shared__ __align__(128) char smem[];
    const uint32_t sb0 = smem_u32(smem);            // A bufs at 0, TILEB
    const uint32_t sbB0 = sb0 + 2 * TILEB;          // B stages
    const int tid  = threadIdx.x;
    const int lane = tid & 31;
    const int wid  = tid >> 5;
    const int wm   = wid & 3;        // 4 warps down M (32 rows)
    const int wn   = wid >> 2;       // 2 warps across N (128 cols)
    const int m0 = blockIdx.x * 128;

    const int l0 = tid, l1 = 256 + tid;
    const int ar0 = l0 >> 2, ac0 = l0 & 3;
    const int ar1 = l1 >> 2, ac1 = l1 & 3;
    const bool av0 = (m0 + ar0) < N_NODES;
    const bool av1 = (m0 + ar1) < N_NODES;
    const float* ap0 = A + (size_t)(m0 + ar0) * KTOT + ac0 * 8;
    const float* ap1 = A + (size_t)(m0 + ar1) * KTOT + ac1 * 8;
    const uint32_t ao0 = ar0 * ROWB + ac0 * 16;
    const uint32_t ao1 = ar1 * ROWB + ac1 * 16;

    float acc[2][16][4];
#pragma unroll
    for (int i = 0; i < 2; i++)
#pragma unroll
        for (int j = 0; j < 16; j++)
#pragma unroll
            for (int q = 0; q < 4; q++) acc[i][j][q] = 0.f;

    const int g = lane >> 3;
    const int r = lane & 7;
    const float4 z4 = make_float4(0.f, 0.f, 0.f, 0.f);

    load_B1<KTOT>(sbB0, tid, 0, B);
    if (NC > 1) load_B1<KTOT>(sbB0 + TILEB2, tid, 1, B);
    if (NC > 2) load_B1<KTOT>(sbB0 + 2 * TILEB2, tid, 2, B);
    {
        float4 p0a = av0 ? *reinterpret_cast<const float4*>(ap0)     : z4;
        float4 p0b = av0 ? *reinterpret_cast<const float4*>(ap0 + 4) : z4;
        float4 p1a = av1 ? *reinterpret_cast<const float4*>(ap1)     : z4;
        float4 p1b = av1 ? *reinterpret_cast<const float4*>(ap1 + 4) : z4;
        cvt_sts16(sb0 + ao0, p0a, p0b);
        cvt_sts16(sb0 + ao1, p1a, p1b);
    }

    for (int c = 0; c < NC; c++) {
        const int rem = NC - 1 - c;
        if (rem >= 2)      asm volatile("cp.async.wait_group 2;" ::: "memory");
        else if (rem == 1) asm volatile("cp.async.wait_group 1;" ::: "memory");
        else               asm volatile("cp.async.wait_group 0;" ::: "memory");
        __syncthreads();

        float4 p0a = z4, p0b = z4, p1a = z4, p1b = z4;
        if (c + 1 < NC) {
            const int k0n = (c + 1) * 32;
            if (av0) {
                p0a = *reinterpret_cast<const float4*>(ap0 + k0n);
                p0b = *reinterpret_cast<const float4*>(ap0 + k0n + 4);
            }
            if (av1) {
                p1a = *reinterpret_cast<const float4*>(ap1 + k0n);
                p1b = *reinterpret_cast<const float4*>(ap1 + k0n + 4);
            }
        }
        if (c + 3 < NC)
            load_B1<KTOT>(sbB0 + ((c + 3) & 3) * TILEB2, tid, c + 3, B);

        const uint32_t sbA = sb0 + (c & 1) * TILEB;
        const uint32_t sbB = sbB0 + (c & 3) * TILEB2;
#pragma unroll
        for (int kk = 0; kk < 2; kk++) {
            uint32_t af[2][4];
#pragma unroll
            for (int ms = 0; ms < 2; ms++) {
                uint32_t arow = wm * 32 + ms * 16 + ((g & 1) << 3) + r;
                uint32_t aoff = arow * ROWB + kk * 32 + ((g >> 1) << 4);
                ldsm_x4(af[ms], sbA + aoff);
            }
#pragma unroll
            for (int nb2 = 0; nb2 < 8; nb2++) {
                uint32_t nrow = wn * 128 + nb2 * 16 + ((g >> 1) << 3) + r;
                uint32_t boff = nrow * ROWB + kk * 32 + ((g & 1) << 4);
                uint32_t bf[4];
                ldsm_x4(bf, sbB + boff);
#pragma unroll
                for (int ms = 0; ms < 2; ms++)
#pragma unroll
                    for (int h = 0; h < 2; h++)
                        mma_f16(acc[ms][nb2 * 2 + h], af[ms], &bf[h * 2]);
            }
        }

        if (c + 1 < NC) {
            const uint32_t sbAn = sb0 + ((c + 1) & 1) * TILEB;
            cvt_sts16(sbAn + ao0, p0a, p0b);
            cvt_sts16(sbAn + ao1, p1a, p1b);
        }
    }

#pragma unroll
    for (int ms = 0; ms < 2; ms++) {
        int grow = m0 + wm * 32 + ms * 16 + (lane >> 2);
#pragma unroll
        for (int nb = 0; nb < 16; nb++) {
            int gcol = wn * 128 + nb * 8 + (lane & 3) * 2;
            *reinterpret_cast<__half2*>(&C[(size_t)grow * ldc + gcol]) =
                __floats2half2_rn(acc[ms][nb][0], acc[ms][nb][1]);
            *reinterpret_cast<__half2*>(&C[(size_t)(grow + 8) * ldc + gcol]) =
                __floats2half2_rn(acc[ms][nb][2], acc[ms][nb][3]);
        }
    }
}

// ==========================================================================
// GEMM2: fp16 A and B via 4-stage cp.async (CTA 128x128, mbase for M split)
// ==========================================================================
static constexpr int STAGEB = 2 * TILEB;
static constexpr int NSTAGE = 4;
static constexpr int SMEMB2 = NSTAGE * STAGEB;      // 81920

template <int KTOT>
__device__ __forceinline__ void load_stage(
    uint32_t sb, int tid, int kc, int m0, int n0,
    const __half* __restrict__ A, const __half* __restrict__ B)
{
    const int k0 = kc * 32;
#pragma unroll
    for (int j = 0; j < 4; j++) {
        int linear = j * 256 + tid;
        int tile   = linear >> 9;
        int within = linear & 511;
        int row    = within >> 2;
        int chunk  = within & 3;
        const __half* base = (tile == 0) ? A : B;
        int grow = ((tile == 0) ? m0 : n0) + row;
        const void* g = base + (size_t)grow * KTOT + k0 + chunk * 8;
        cp16(sb + tile * TILEB + row * ROWB + chunk * 16, g);
    }
    asm volatile("cp.async.commit_group;" ::: "memory");
}

template <int KTOT>
__global__ __launch_bounds__(256, 2) void k_mma(
    const __half* __restrict__ A, const __half* __restrict__ B,
    __half* __restrict__ C, int ldc, int mbase)
{
    constexpr int NC = KTOT / 32;
    extern __shared__ __align__(128) char smem[];
    const uint32_t sb0 = smem_u32(smem);
    const int tid  = threadIdx.x;
    const int lane = tid & 31;
    const int wid  = tid >> 5;
    const int wm   = wid & 3;
    const int wn   = wid >> 2;
    const int m0 = (mbase + blockIdx.y) * 128, n0 = blockIdx.x * 128;

    float acc[2][8][4];
#pragma unroll
    for (int i = 0; i < 2; i++)
#pragma unroll
        for (int j = 0; j < 8; j++)
#pragma unroll
            for (int q = 0; q < 4; q++) acc[i][j][q] = 0.f;

    const int g = lane >> 3;
    const int r = lane & 7;

    load_stage<KTOT>(sb0, tid, 0, m0, n0, A, B);
    if (NC > 1) load_stage<KTOT>(sb0 + STAGEB, tid, 1, m0, n0, A, B);
    if (NC > 2) load_stage<KTOT>(sb0 + 2 * STAGEB, tid, 2, m0, n0, A, B);

    for (int c = 0; c < NC; c++) {
        const int rem = NC - 1 - c;
        if (rem >= 2)      asm volatile("cp.async.wait_group 2;" ::: "memory");
        else if (rem == 1) asm volatile("cp.async.wait_group 1;" ::: "memory");
        else               asm volatile("cp.async.wait_group 0;" ::: "memory");
        __syncthreads();

        if (c + 3 < NC)
            load_stage<KTOT>(sb0 + ((c + 3) % NSTAGE) * STAGEB, tid, c + 3,
                             m0, n0, A, B);

        const uint32_t sb = sb0 + (c % NSTAGE) * STAGEB;
#pragma unroll
        for (int kk = 0; kk < 2; kk++) {
            uint32_t af[2][4];
#pragma unroll
            for (int ms = 0; ms < 2; ms++) {
                uint32_t arow = wm * 32 + ms * 16 + ((g & 1) << 3) + r;
                uint32_t aoff = arow * ROWB + kk * 32 + ((g >> 1) << 4);
                ldsm_x4(af[ms], sb + aoff);
            }
#pragma unroll
            for (int nb2 = 0; nb2 < 4; nb2++) {
                uint32_t nrow = wn * 64 + nb2 * 16 + ((g >> 1) << 3) + r;
                uint32_t boff = nrow * ROWB + kk * 32 + ((g & 1) << 4);
                uint32_t bf[4];
                ldsm_x4(bf, sb + TILEB + boff);
#pragma unroll
                for (int ms = 0; ms < 2; ms++)
#pragma unroll
                    for (int h = 0; h < 2; h++)
                        mma_f16(acc[ms][nb2 * 2 + h], af[ms], &bf[h * 2]);
            }
        }
        __syncthreads();
    }

#pragma unroll
    for (int ms = 0; ms < 2; ms++) {
        int grow = m0 + wm * 32 + ms * 16 + (lane >> 2);
#pragma unroll
        for (int nb = 0; nb < 8; nb++) {
            int gcol = n0 + wn * 64 + nb * 8 + (lane & 3) * 2;
            *reinterpret_cast<__half2*>(&C[(size_t)grow * ldc + gcol]) =
                __floats2half2_rn(acc[ms][nb][0], acc[ms][nb][1]);
            *reinterpret_cast<__half2*>(&C[(size_t)(grow + 8) * ldc + gcol]) =
                __floats2half2_rn(acc[ms][nb][2], acc[ms][nb][3]);
        }
    }
}

// ------------------------------------------------------------------------
// aggregation: warp-per-node fp16 gather, fp32 accumulate
// k_agg1 takes a node range [node_base, node_end) for layer-2 pipelining
// ------------------------------------------------------------------------
__global__ __launch_bounds__(256) void k_agg1(const float* __restrict__ b1,
                                              int node_base, int node_end) {
    int node = node_base + blockIdx.x * 8 + (threadIdx.x >> 5);
    if (node >= node_end) return;
    int lane = threadIdx.x & 31;
    float wd = g_dinv[node];

    float a[8];
    {
        uint4 u = *reinterpret_cast<const uint4*>(&g_H1h[(size_t)node * HIDDEN + lane * 8]);
        const __half2* h = reinterpret_cast<const __half2*>(&u);
        float sw = wd * wd;
#pragma unroll
        for (int t = 0; t < 4; t++) {
            float2 f = __half22float2(h[t]);
            a[2 * t]     = f.x * sw;
            a[2 * t + 1] = f.y * sw;
        }
    }

    int beg = g_off[node], end = g_off[node + 1];
    int i = beg;
    for (; i + 3 < end; i += 4) {
        int s0 = g_csr_src[i];
        int s1 = g_csr_src[i + 1];
        int s2 = g_csr_src[i + 2];
        int s3 = g_csr_src[i + 3];
        uint4 u0 = *reinterpret_cast<const uint4*>(&g_H1h[(size_t)s0 * HIDDEN + lane * 8]);
        uint4 u1 = *reinterpret_cast<const uint4*>(&g_H1h[(size_t)s1 * HIDDEN + lane * 8]);
        uint4 u2 = *reinterpret_cast<const uint4*>(&g_H1h[(size_t)s2 * HIDDEN + lane * 8]);
        uint4 u3 = *reinterpret_cast<const uint4*>(&g_H1h[(size_t)s3 * HIDDEN + lane * 8]);
        float w0 = g_dinv[s0] * wd;
        float w1 = g_dinv[s1] * wd;
        float w2 = g_dinv[s2] * wd;
        float w3 = g_dinv[s3] * wd;
        acc8(a, u0, w0);
        acc8(a, u1, w1);
        acc8(a, u2, w2);
        acc8(a, u3, w3);
    }
    for (; i < end; i++) {
        int s0 = g_csr_src[i];
        float w0 = g_dinv[s0] * wd;
        uint4 u0 = *reinterpret_cast<const uint4*>(&g_H1h[(size_t)s0 * HIDDEN + lane * 8]);
        acc8(a, u0, w0);
    }

    float4 bb0 = *reinterpret_cast<const float4*>(&b1[lane * 8]);
    float4 bb1 = *reinterpret_cast<const float4*>(&b1[lane * 8 + 4]);
    float rr[8];
    rr[0] = fmaxf(a[0] + bb0.x, 0.f); rr[1] = fmaxf(a[1] + bb0.y, 0.f);
    rr[2] = fmaxf(a[2] + bb0.z, 0.f); rr[3] = fmaxf(a[3] + bb0.w, 0.f);
    rr[4] = fmaxf(a[4] + bb1.x, 0.f); rr[5] = fmaxf(a[5] + bb1.y, 0.f);
    rr[6] = fmaxf(a[6] + bb1.z, 0.f); rr[7] = fmaxf(a[7] + bb1.w, 0.f);

    __half2 o[4];
#pragma unroll
    for (int t = 0; t < 4; t++) o[t] = __floats2half2_rn(rr[2 * t], rr[2 * t + 1]);
    *reinterpret_cast<uint4*>(&g_h1a[(size_t)node * HIDDEN + lane * 8]) =
        *reinterpret_cast<const uint4*>(o);
}

__global__ __launch_bounds__(256) void k_agg2(const float* __restrict__ b2,
                                              float* __restrict__ out) {
    int node = blockIdx.x * 8 + (threadIdx.x >> 5);
    if (node >= N_NODES) return;
    int lane = threadIdx.x & 31;
    float wd = g_dinv[node];

    float a[4];
    {
        uint2 u = *reinterpret_cast<const uint2*>(&g_H2h[(size_t)node * OUT_FEATS + lane * 4]);
        const __half2* h = reinterpret_cast<const __half2*>(&u);
        float sw = wd * wd;
#pragma unroll
        for (int t = 0; t < 2; t++) {
            float2 f = __half22float2(h[t]);
            a[2 * t]     = f.x * sw;
            a[2 * t + 1] = f.y * sw;
        }
    }

    int beg = g_off[node], end = g_off[node + 1];
    int i = beg;
    for (; i + 3 < end; i += 4) {
        int s0 = g_csr_src[i];
        int s1 = g_csr_src[i + 1];
        int s2 = g_csr_src[i + 2];
        int s3 = g_csr_src[i + 3];
        uint2 u0 = *reinterpret_cast<const uint2*>(&g_H2h[(size_t)s0 * OUT_FEATS + lane * 4]);
        uint2 u1 = *reinterpret_cast<const uint2*>(&g_H2h[(size_t)s1 * OUT_FEATS + lane * 4]);
        uint2 u2 = *reinterpret_cast<const uint2*>(&g_H2h[(size_t)s2 * OUT_FEATS + lane * 4]);
        uint2 u3 = *reinterpret_cast<const uint2*>(&g_H2h[(size_t)s3 * OUT_FEATS + lane * 4]);
        float w0 = g_dinv[s0] * wd;
        float w1 = g_dinv[s1] * wd;
        float w2 = g_dinv[s2] * wd;
        float w3 = g_dinv[s3] * wd;
        acc4(a, u0, w0);
        acc4(a, u1, w1);
        acc4(a, u2, w2);
        acc4(a, u3, w3);
    }
    for (; i < end; i++) {
        int s0 = g_csr_src[i];
        float w0 = g_dinv[s0] * wd;
        uint2 u0 = *reinterpret_cast<const uint2*>(&g_H2h[(size_t)s0 * OUT_FEATS + lane * 4]);
        acc4(a, u0, w0);
    }

    float4 bb = *reinterpret_cast<const float4*>(&b2[lane * 4]);
    *reinterpret_cast<float4*>(&out[(size_t)node * OUT_FEATS + lane * 4]) =
        make_float4(a[0] + bb.x, a[1] + bb.y, a[2] + bb.z, a[3] + bb.w);
}

// ------------------------------------------------------------------------
// launch
// ------------------------------------------------------------------------
extern "C" void kernel_launch(void* const* d_in, const int* in_sizes, int n_in,
                              void* d_out, int out_size) {
    const float* x  = (const float*)d_in[0];
    const int*   ei = (const int*)d_in[1];
    const float* W1 = (const float*)d_in[2];
    const float* b1 = (const float*)d_in[3];
    const float* W2 = (const float*)d_in[4];
    const float* b2 = (const float*)d_in[5];
    float* out = (float*)d_out;

    const int* src = ei;
    const int* dst = ei + N_EDGES;

    __half *w1h, *H1h, *h1a, *w2h, *H2h;
    cudaGetSymbolAddress((void**)&w1h, g_w1h);
    cudaGetSymbolAddress((void**)&H1h, g_H1h);
    cudaGetSymbolAddress((void**)&h1a, g_h1a);
    cudaGetSymbolAddress((void**)&w2h, g_w2h);
    cudaGetSymbolAddress((void**)&H2h, g_H2h);

    static cudaStream_t s_side = nullptr;
    static cudaEvent_t ev_fork = nullptr, ev_csr = nullptr, ev_h0 = nullptr, ev_g2h0 = nullptr;
    if (s_side == nullptr) {
        cudaStreamCreateWithFlags(&s_side, cudaStreamNonBlocking);
        cudaEventCreateWithFlags(&ev_fork, cudaEventDisableTiming);
        cudaEventCreateWithFlags(&ev_csr,  cudaEventDisableTiming);
        cudaEventCreateWithFlags(&ev_h0,   cudaEventDisableTiming);
        cudaEventCreateWithFlags(&ev_g2h0, cudaEventDisableTiming);
        cudaFuncSetAttribute(k_mma_xA<IN_FEATS>, cudaFuncAttributeMaxDynamicSharedMemorySize, SMEMB1);
        cudaFuncSetAttribute(k_mma<HIDDEN>,      cudaFuncAttributeMaxDynamicSharedMemorySize, SMEMB2);
    }

    // fork
    cudaEventRecord(ev_fork, 0);
    cudaStreamWaitEvent(s_side, ev_fork, 0);

    // side: CSR build + W2 transpose
    k_zero_cnt<<<(N_NODES + 255) / 256, 256, 0, s_side>>>();
    k_count<<<(N_EDGES / 8 + 255) / 256, 256, 0, s_side>>>(dst);
    k_bsum<<<SCAN_NBLK, 256, 0, s_side>>>();
    k_bscan<<<1, 256, 0, s_side>>>();
    k_off<<<SCAN_NBLK, 256, 0, s_side>>>();
    k_fill<<<(N_EDGES / 8 + 255) / 256, 256, 0, s_side>>>(src, dst);
    k_wT<<<(OUT_FEATS * HIDDEN + 255) / 256, 256, 0, s_side>>>(W2, HIDDEN, OUT_FEATS, w2h);
    cudaEventRecord(ev_csr, s_side);

    // main: W1 transpose, fused-convert GEMM1 (128x256 tiles, R11 config)
    k_wT<<<(HIDDEN * IN_FEATS + 255) / 256, 256>>>(W1, IN_FEATS, HIDDEN, w1h);
    k_mma_xA<IN_FEATS><<<M_PAD / 128, 256, SMEMB1>>>(x, w1h, H1h, HIDDEN);

    // join CSR; agg1 half 0
    cudaStreamWaitEvent(0, ev_csr, 0);
    k_agg1<<<HALF0_NODES / 8, 256>>>(b1, 0, HALF0_NODES);
    cudaEventRecord(ev_h0, 0);

    // side: GEMM2 on rows [0, HALF0_NODES) while main does agg1 half 1
    cudaStreamWaitEvent(s_side, ev_h0, 0);
    k_mma<HIDDEN><<<dim3(OUT_FEATS / 128, HALF0_MBLK), 256, SMEMB2, s_side>>>(
        h1a, w2h, H2h, OUT_FEATS, 0);
    cudaEventRecord(ev_g2h0, s_side);

    // main: agg1 half 1, then GEMM2 on remaining rows
    k_agg1<<<(N_NODES - HALF0_NODES + 7) / 8, 256>>>(b1, HALF0_NODES, N_NODES);
    k_mma<HIDDEN><<<dim3(OUT_FEATS / 128, HALF1_MBLK), 256, SMEMB2>>>(
        h1a, w2h, H2h, OUT_FEATS, HALF0_MBLK);

    // join: agg2 needs full H2h
    cudaStreamWaitEvent(0, ev_g2h0, 0);
    k_agg2<<<(N_NODES + 7) / 8, 256>>>(b2, out);
}

// round 14
// speedup vs baseline: 1.0260x; 1.0056x over previous
#include <cuda_runtime.h>
#include <cuda_fp16.h>
#include <cstdint>

#define N_NODES 50000
#define M_PAD   50048
#define N_EDGES 800000
#define IN_FEATS 768
#define HIDDEN 256
#define OUT_FEATS 128
#define SCAN_NBLK ((N_NODES + 255) / 256)   // 196

// ------------------------------------------------------------------------
// device scratch
// ------------------------------------------------------------------------
__device__ int   g_cnt[N_NODES];
__device__ int   g_off[N_NODES + 1];
__device__ int   g_cur[N_NODES];
__device__ int   g_csr_src[N_EDGES];
__device__ float g_dinv[N_NODES];
__device__ int   g_bsum[SCAN_NBLK];
__device__ int   g_bpre[SCAN_NBLK];

__device__ __half g_w1h [HIDDEN * IN_FEATS];          // fp16(W1^T)
__device__ __half g_H1h [(size_t)M_PAD * HIDDEN];     // fp16(X @ W1)  pre-agg
__device__ __half g_h1a [(size_t)M_PAD * HIDDEN];     // fp16(relu(agg+b1)); pad rows stay 0
__device__ __half g_w2h [OUT_FEATS * HIDDEN];         // fp16(W2^T)
__device__ __half g_H2h [(size_t)M_PAD * OUT_FEATS];  // fp16(h1a @ W2) pre-agg

// ------------------------------------------------------------------------
// PTX helpers
// ------------------------------------------------------------------------
__device__ __forceinline__ uint32_t smem_u32(const void* p) {
    uint32_t a;
    asm("{ .reg .u64 t; cvta.to.shared.u64 t, %1; cvt.u32.u64 %0, t; }"
        : "=r"(a) : "l"(p));
    return a;
}

__device__ __forceinline__ void cp16(uint32_t dst, const void* src) {
    asm volatile("cp.async.cg.shared.global [%0], [%1], 16;" :: "r"(dst), "l"(src) : "memory");
}

__device__ __forceinline__ void ldsm_x4(uint32_t* r, uint32_t addr) {
    asm volatile("ldmatrix.sync.aligned.m8n8.x4.shared.b16 {%0,%1,%2,%3}, [%4];"
                 : "=r"(r[0]), "=r"(r[1]), "=r"(r[2]), "=r"(r[3]) : "r"(addr));
}

__device__ __forceinline__ void mma_f16(float* d, const uint32_t* a, const uint32_t* b) {
    asm volatile(
        "mma.sync.aligned.m16n8k16.row.col.f32.f16.f16.f32 "
        "{%0,%1,%2,%3}, {%4,%5,%6,%7}, {%8,%9}, {%0,%1,%2,%3};"
        : "+f"(d[0]), "+f"(d[1]), "+f"(d[2]), "+f"(d[3])
        : "r"(a[0]), "r"(a[1]), "r"(a[2]), "r"(a[3]), "r"(b[0]), "r"(b[1]));
}

// convert 8 fp32 -> 8 fp16 and store 16B to smem
__device__ __forceinline__ void cvt_sts16(uint32_t dst, const float4& lo, const float4& hi) {
    __half2 h[4];
    h[0] = __floats2half2_rn(lo.x, lo.y);
    h[1] = __floats2half2_rn(lo.z, lo.w);
    h[2] = __floats2half2_rn(hi.x, hi.y);
    h[3] = __floats2half2_rn(hi.z, hi.w);
    uint4 u = *reinterpret_cast<const uint4*>(h);
    asm volatile("st.shared.v4.b32 [%0], {%1,%2,%3,%4};"
                 :: "r"(dst), "r"(u.x), "r"(u.y), "r"(u.z), "r"(u.w) : "memory");
}

__device__ __forceinline__ void acc8(float* a, const uint4& u, float w) {
    const __half2* h = reinterpret_cast<const __half2*>(&u);
#pragma unroll
    for (int t = 0; t < 4; t++) {
        float2 f = __half22float2(h[t]);
        a[2 * t]     += f.x * w;
        a[2 * t + 1] += f.y * w;
    }
}

__device__ __forceinline__ void acc4(float* a, const uint2& u, float w) {
    const __half2* h = reinterpret_cast<const __half2*>(&u);
#pragma unroll
    for (int t = 0; t < 2; t++) {
        float2 f = __half22float2(h[t]);
        a[2 * t]     += f.x * w;
        a[2 * t + 1] += f.y * w;
    }
}

// ------------------------------------------------------------------------
// CSR build
// ------------------------------------------------------------------------
__global__ void k_zero_cnt() {
    int i = blockIdx.x * blockDim.x + threadIdx.x;
    if (i < N_NODES) g_cnt[i] = 0;
}

__global__ void k_count(const int* __restrict__ dst) {
    int e8 = (blockIdx.x * blockDim.x + threadIdx.x) * 8;
    if (e8 < N_EDGES) {
        int4 d0 = *reinterpret_cast<const int4*>(dst + e8);
        int4 d1 = *reinterpret_cast<const int4*>(dst + e8 + 4);
        atomicAdd(&g_cnt[d0.x], 1); atomicAdd(&g_cnt[d0.y], 1);
        atomicAdd(&g_cnt[d0.z], 1); atomicAdd(&g_cnt[d0.w], 1);
        atomicAdd(&g_cnt[d1.x], 1); atomicAdd(&g_cnt[d1.y], 1);
        atomicAdd(&g_cnt[d1.z], 1); atomicAdd(&g_cnt[d1.w], 1);
    }
}

__global__ void k_bsum() {
    __shared__ int s[256];
    int t = threadIdx.x;
    int i = blockIdx.x * 256 + t;
    int v = (i < N_NODES) ? g_cnt[i] : 0;
    s[t] = v;
    __syncthreads();
    for (int o = 1; o < 256; o <<= 1) {
        int u = (t >= o) ? s[t - o] : 0;
        __syncthreads();
        s[t] += u;
        __syncthreads();
    }
    if (t == 255) g_bsum[blockIdx.x] = s[255];
}

__global__ void k_bscan() {
    __shared__ int s[256];
    int t = threadIdx.x;
    int v = (t < SCAN_NBLK) ? g_bsum[t] : 0;
    s[t] = v;
    __syncthreads();
    for (int o = 1; o < 256; o <<= 1) {
        int u = (t >= o) ? s[t - o] : 0;
        __syncthreads();
        s[t] += u;
        __syncthreads();
    }
    if (t < SCAN_NBLK) g_bpre[t] = s[t] - v;
}

__global__ void k_off() {
    __shared__ int s[256];
    int t = threadIdx.x;
    int i = blockIdx.x * 256 + t;
    int v = (i < N_NODES) ? g_cnt[i] : 0;
    s[t] = v;
    __syncthreads();
    for (int o = 1; o < 256; o <<= 1) {
        int u = (t >= o) ? s[t - o] : 0;
        __syncthreads();
        s[t] += u;
        __syncthreads();
    }
    if (i < N_NODES) {
        int pre = g_bpre[blockIdx.x] + s[t] - v;
        g_off[i] = pre;
        g_cur[i] = pre;
        g_dinv[i] = rsqrtf((float)(v + 1));
    }
    if (i == 0) g_off[N_NODES] = N_EDGES;
}

__global__ void k_fill(const int* __restrict__ src, const int* __restrict__ dst) {
    int e8 = (blockIdx.x * blockDim.x + threadIdx.x) * 8;
    if (e8 < N_EDGES) {
        int4 d0 = *reinterpret_cast<const int4*>(dst + e8);
        int4 d1 = *reinterpret_cast<const int4*>(dst + e8 + 4);
        int4 s0 = *reinterpret_cast<const int4*>(src + e8);
        int4 s1 = *reinterpret_cast<const int4*>(src + e8 + 4);
        g_csr_src[atomicAdd(&g_cur[d0.x], 1)] = s0.x;
        g_csr_src[atomicAdd(&g_cur[d0.y], 1)] = s0.y;
        g_csr_src[atomicAdd(&g_cur[d0.z], 1)] = s0.z;
        g_csr_src[atomicAdd(&g_cur[d0.w], 1)] = s0.w;
        g_csr_src[atomicAdd(&g_cur[d1.x], 1)] = s1.x;
        g_csr_src[atomicAdd(&g_cur[d1.y], 1)] = s1.y;
        g_csr_src[atomicAdd(&g_cur[d1.z], 1)] = s1.z;
        g_csr_src[atomicAdd(&g_cur[d1.w], 1)] = s1.w;
    }
}

// transpose weights to fp16: W[K][N] -> Wt[N][K]
__global__ void k_wT(const float* __restrict__ W, int K, int N,
                     __half* __restrict__ out) {
    int idx = blockIdx.x * blockDim.x + threadIdx.x;
    if (idx >= N * K) return;
    int n = idx / K, k = idx % K;
    out[idx] = __float2half_rn(W[(size_t)k * N + n]);
}

// ------------------------------------------------------------------------
// GEMM constants
// ------------------------------------------------------------------------
static constexpr int ROWB   = 80;
static constexpr int TILEB  = 128 * ROWB;            // 10240 (128-row tile)
static constexpr int TILEB2 = 256 * ROWB;            // 20480 (256-row tile)

// ==========================================================================
// GEMM1: C[M,256] = fp16(A_fp32) * B^T, CTA tile 128x256, 512 threads
// (16 warps, warp tile 32x64).  A converted on the fly (1 chunk/thread,
// double buffer); B 4-stage cp.async.  smem = 102400, 1 CTA/SM.
// ==========================================================================
static constexpr int SMEMB1 = 2 * TILEB + 4 * TILEB2;   // 102400

template <int KTOT>
__device__ __forceinline__ void load_B1(
    uint32_t sbB, int tid, int kc, const __half* __restrict__ B)
{
    const int k0 = kc * 32;
#pragma unroll
    for (int j = 0; j < 2; j++) {                   // 256 rows * 4 chunks / 512 thr
        int linear = j * 512 + tid;
        int row    = linear >> 2;
        int chunk  = linear & 3;
        cp16(sbB + row * ROWB + chunk * 16,
             B + (size_t)row * KTOT + k0 + chunk * 8);
    }
    asm volatile("cp.async.commit_group;" ::: "memory");
}

template <int KTOT>
__global__ __launch_bounds__(512, 1) void k_mma_xA(
    const float* __restrict__ A,        // fp32 [N_NODES, KTOT]
    const __half* __restrict__ B,       // fp16 [256, KTOT]
    __half* __restrict__ C, int ldc)
{
    constexpr int NC = KTOT / 32;
    extern __shared__ __align__(128) char smem[];
    const uint32_t sb0 = smem_u32(smem);            // A bufs at 0, TILEB
    const uint32_t sbB0 = sb0 + 2 * TILEB;          // B stages
    const int tid  = threadIdx.x;
    const int lane = tid & 31;
    const int wid  = tid >> 5;
    const int wm   = wid & 3;        // 4 warps down M (32 rows each)
    const int wn   = wid >> 2;       // 4 warps across N (64 cols each)
    const int m0 = blockIdx.x * 128;

    // one A chunk (16B fp16 = 8 source fp32) per thread: 128 rows * 4 chunks = 512
    const int ar = tid >> 2, ac = tid & 3;
    const bool av = (m0 + ar) < N_NODES;
    const float* ap = A + (size_t)(m0 + ar) * KTOT + ac * 8;
    const uint32_t ao = ar * ROWB + ac * 16;

    float acc[2][8][4];
#pragma unroll
    for (int i = 0; i < 2; i++)
#pragma unroll
        for (int j = 0; j < 8; j++)
#pragma unroll
            for (int q = 0; q < 4; q++) acc[i][j][q] = 0.f;

    const int g = lane >> 3;
    const int r = lane & 7;
    const float4 z4 = make_float4(0.f, 0.f, 0.f, 0.f);

    load_B1<KTOT>(sbB0, tid, 0, B);
    if (NC > 1) load_B1<KTOT>(sbB0 + TILEB2, tid, 1, B);
    if (NC > 2) load_B1<KTOT>(sbB0 + 2 * TILEB2, tid, 2, B);
    {
        float4 pa = av ? *reinterpret_cast<const float4*>(ap)     : z4;
        float4 pb = av ? *reinterpret_cast<const float4*>(ap + 4) : z4;
        cvt_sts16(sb0 + ao, pa, pb);
    }

    for (int c = 0; c < NC; c++) {
        const int rem = NC - 1 - c;
        if (rem >= 2)      asm volatile("cp.async.wait_group 2;" ::: "memory");
        else if (rem == 1) asm volatile("cp.async.wait_group 1;" ::: "memory");
        else               asm volatile("cp.async.wait_group 0;" ::: "memory");
        __syncthreads();

        float4 pa = z4, pb = z4;
        if (c + 1 < NC) {
            const int k0n = (c + 1) * 32;
            if (av) {
                pa = *reinterpret_cast<const float4*>(ap + k0n);
                pb = *reinterpret_cast<const float4*>(ap + k0n + 4);
            }
        }
        if (c + 3 < NC)
            load_B1<KTOT>(sbB0 + ((c + 3) & 3) * TILEB2, tid, c + 3, B);

        const uint32_t sbA = sb0 + (c & 1) * TILEB;
        const uint32_t sbB = sbB0 + (c & 3) * TILEB2;
#pragma unroll
        for (int kk = 0; kk < 2; kk++) {
            uint32_t af[2][4];
#pragma unroll
            for (int ms = 0; ms < 2; ms++) {
                uint32_t arow = wm * 32 + ms * 16 + ((g & 1) << 3) + r;
                uint32_t aoff = arow * ROWB + kk * 32 + ((g >> 1) << 4);
                ldsm_x4(af[ms], sbA + aoff);
            }
#pragma unroll
            for (int nb2 = 0; nb2 < 4; nb2++) {
                uint32_t nrow = wn * 64 + nb2 * 16 + ((g >> 1) << 3) + r;
                uint32_t boff = nrow * ROWB + kk * 32 + ((g & 1) << 4);
                uint32_t bf[4];
                ldsm_x4(bf, sbB + boff);
#pragma unroll
                for (int ms = 0; ms < 2; ms++)
#pragma unroll
                    for (int h = 0; h < 2; h++)
                        mma_f16(acc[ms][nb2 * 2 + h], af[ms], &bf[h * 2]);
            }
        }

        if (c + 1 < NC) {
            const uint32_t sbAn = sb0 + ((c + 1) & 1) * TILEB;
            cvt_sts16(sbAn + ao, pa, pb);
        }
    }

#pragma unroll
    for (int ms = 0; ms < 2; ms++) {
        int grow = m0 + wm * 32 + ms * 16 + (lane >> 2);
#pragma unroll
        for (int nb = 0; nb < 8; nb++) {
            int gcol = wn * 64 + nb * 8 + (lane & 3) * 2;
            *reinterpret_cast<__half2*>(&C[(size_t)grow * ldc + gcol]) =
                __floats2half2_rn(acc[ms][nb][0], acc[ms][nb][1]);
            *reinterpret_cast<__half2*>(&C[(size_t)(grow + 8) * ldc + gcol]) =
                __floats2half2_rn(acc[ms][nb][2], acc[ms][nb][3]);
        }
    }
}

// ==========================================================================
// GEMM2: fp16 A and B via 4-stage cp.async (CTA 128x128, 256 threads)
// ==========================================================================
static constexpr int STAGEB = 2 * TILEB;
static constexpr int NSTAGE = 4;
static constexpr int SMEMB2 = NSTAGE * STAGEB;      // 81920

template <int KTOT>
__device__ __forceinline__ void load_stage(
    uint32_t sb, int tid, int kc, int m0, int n0,
    const __half* __restrict__ A, const __half* __restrict__ B)
{
    const int k0 = kc * 32;
#pragma unroll
    for (int j = 0; j < 4; j++) {
        int linear = j * 256 + tid;
        int tile   = linear >> 9;
        int within = linear & 511;
        int row    = within >> 2;
        int chunk  = within & 3;
        const __half* base = (tile == 0) ? A : B;
        int grow = ((tile == 0) ? m0 : n0) + row;
        const void* g = base + (size_t)grow * KTOT + k0 + chunk * 8;
        cp16(sb + tile * TILEB + row * ROWB + chunk * 16, g);
    }
    asm volatile("cp.async.commit_group;" ::: "memory");
}

template <int KTOT>
__global__ __launch_bounds__(256, 2) void k_mma(
    const __half* __restrict__ A, const __half* __restrict__ B,
    __half* __restrict__ C, int ldc)
{
    constexpr int NC = KTOT / 32;
    extern __shared__ __align__(128) char smem[];
    const uint32_t sb0 = smem_u32(smem);
    const int tid  = threadIdx.x;
    const int lane = tid & 31;
    const int wid  = tid >> 5;
    const int wm   = wid & 3;
    const int wn   = wid >> 2;
    const int m0 = blockIdx.y * 128, n0 = blockIdx.x * 128;

    float acc[2][8][4];
#pragma unroll
    for (int i = 0; i < 2; i++)
#pragma unroll
        for (int j = 0; j < 8; j++)
#pragma unroll
            for (int q = 0; q < 4; q++) acc[i][j][q] = 0.f;

    const int g = lane >> 3;
    const int r = lane & 7;

    load_stage<KTOT>(sb0, tid, 0, m0, n0, A, B);
    if (NC > 1) load_stage<KTOT>(sb0 + STAGEB, tid, 1, m0, n0, A, B);
    if (NC > 2) load_stage<KTOT>(sb0 + 2 * STAGEB, tid, 2, m0, n0, A, B);

    for (int c = 0; c < NC; c++) {
        const int rem = NC - 1 - c;
        if (rem >= 2)      asm volatile("cp.async.wait_group 2;" ::: "memory");
        else if (rem == 1) asm volatile("cp.async.wait_group 1;" ::: "memory");
        else               asm volatile("cp.async.wait_group 0;" ::: "memory");
        __syncthreads();

        if (c + 3 < NC)
            load_stage<KTOT>(sb0 + ((c + 3) % NSTAGE) * STAGEB, tid, c + 3,
                             m0, n0, A, B);

        const uint32_t sb = sb0 + (c % NSTAGE) * STAGEB;
#pragma unroll
        for (int kk = 0; kk < 2; kk++) {
            uint32_t af[2][4];
#pragma unroll
            for (int ms = 0; ms < 2; ms++) {
                uint32_t arow = wm * 32 + ms * 16 + ((g & 1) << 3) + r;
                uint32_t aoff = arow * ROWB + kk * 32 + ((g >> 1) << 4);
                ldsm_x4(af[ms], sb + aoff);
            }
#pragma unroll
            for (int nb2 = 0; nb2 < 4; nb2++) {
                uint32_t nrow = wn * 64 + nb2 * 16 + ((g >> 1) << 3) + r;
                uint32_t boff = nrow * ROWB + kk * 32 + ((g & 1) << 4);
                uint32_t bf[4];
                ldsm_x4(bf, sb + TILEB + boff);
#pragma unroll
                for (int ms = 0; ms < 2; ms++)
#pragma unroll
                    for (int h = 0; h < 2; h++)
                        mma_f16(acc[ms][nb2 * 2 + h], af[ms], &bf[h * 2]);
            }
        }
        __syncthreads();
    }

#pragma unroll
    for (int ms = 0; ms < 2; ms++) {
        int grow = m0 + wm * 32 + ms * 16 + (lane >> 2);
#pragma unroll
        for (int nb = 0; nb < 8; nb++) {
            int gcol = n0 + wn * 64 + nb * 8 + (lane & 3) * 2;
            *reinterpret_cast<__half2*>(&C[(size_t)grow * ldc + gcol]) =
                __floats2half2_rn(acc[ms][nb][0], acc[ms][nb][1]);
            *reinterpret_cast<__half2*>(&C[(size_t)(grow + 8) * ldc + gcol]) =
                __floats2half2_rn(acc[ms][nb][2], acc[ms][nb][3]);
        }
    }
}

// ------------------------------------------------------------------------
// aggregation: warp-per-node fp16 gather, fp32 accumulate
// ------------------------------------------------------------------------
__global__ __launch_bounds__(256) void k_agg1(const float* __restrict__ b1) {
    int node = blockIdx.x * 8 + (threadIdx.x >> 5);
    if (node >= N_NODES) return;
    int lane = threadIdx.x & 31;
    float wd = g_dinv[node];

    float a[8];
    {
        uint4 u = *reinterpret_cast<const uint4*>(&g_H1h[(size_t)node * HIDDEN + lane * 8]);
        const __half2* h = reinterpret_cast<const __half2*>(&u);
        float sw = wd * wd;
#pragma unroll
        for (int t = 0; t < 4; t++) {
            float2 f = __half22float2(h[t]);
            a[2 * t]     = f.x * sw;
            a[2 * t + 1] = f.y * sw;
        }
    }

    int beg = g_off[node], end = g_off[node + 1];
    int i = beg;
    for (; i + 3 < end; i += 4) {
        int s0 = g_csr_src[i];
        int s1 = g_csr_src[i + 1];
        int s2 = g_csr_src[i + 2];
        int s3 = g_csr_src[i + 3];
        uint4 u0 = *reinterpret_cast<const uint4*>(&g_H1h[(size_t)s0 * HIDDEN + lane * 8]);
        uint4 u1 = *reinterpret_cast<const uint4*>(&g_H1h[(size_t)s1 * HIDDEN + lane * 8]);
        uint4 u2 = *reinterpret_cast<const uint4*>(&g_H1h[(size_t)s2 * HIDDEN + lane * 8]);
        uint4 u3 = *reinterpret_cast<const uint4*>(&g_H1h[(size_t)s3 * HIDDEN + lane * 8]);
        float w0 = g_dinv[s0] * wd;
        float w1 = g_dinv[s1] * wd;
        float w2 = g_dinv[s2] * wd;
        float w3 = g_dinv[s3] * wd;
        acc8(a, u0, w0);
        acc8(a, u1, w1);
        acc8(a, u2, w2);
        acc8(a, u3, w3);
    }
    for (; i < end; i++) {
        int s0 = g_csr_src[i];
        float w0 = g_dinv[s0] * wd;
        uint4 u0 = *reinterpret_cast<const uint4*>(&g_H1h[(size_t)s0 * HIDDEN + lane * 8]);
        acc8(a, u0, w0);
    }

    float4 bb0 = *reinterpret_cast<const float4*>(&b1[lane * 8]);
    float4 bb1 = *reinterpret_cast<const float4*>(&b1[lane * 8 + 4]);
    float rr[8];
    rr[0] = fmaxf(a[0] + bb0.x, 0.f); rr[1] = fmaxf(a[1] + bb0.y, 0.f);
    rr[2] = fmaxf(a[2] + bb0.z, 0.f); rr[3] = fmaxf(a[3] + bb0.w, 0.f);
    rr[4] = fmaxf(a[4] + bb1.x, 0.f); rr[5] = fmaxf(a[5] + bb1.y, 0.f);
    rr[6] = fmaxf(a[6] + bb1.z, 0.f); rr[7] = fmaxf(a[7] + bb1.w, 0.f);

    __half2 o[4];
#pragma unroll
    for (int t = 0; t < 4; t++) o[t] = __floats2half2_rn(rr[2 * t], rr[2 * t + 1]);
    *reinterpret_cast<uint4*>(&g_h1a[(size_t)node * HIDDEN + lane * 8]) =
        *reinterpret_cast<const uint4*>(o);
}

__global__ __launch_bounds__(256) void k_agg2(const float* __restrict__ b2,
                                              float* __restrict__ out) {
    int node = blockIdx.x * 8 + (threadIdx.x >> 5);
    if (node >= N_NODES) return;
    int lane = threadIdx.x & 31;
    float wd = g_dinv[node];

    float a[4];
    {
        uint2 u = *reinterpret_cast<const uint2*>(&g_H2h[(size_t)node * OUT_FEATS + lane * 4]);
        const __half2* h = reinterpret_cast<const __half2*>(&u);
        float sw = wd * wd;
#pragma unroll
        for (int t = 0; t < 2; t++) {
            float2 f = __half22float2(h[t]);
            a[2 * t]     = f.x * sw;
            a[2 * t + 1] = f.y * sw;
        }
    }

    int beg = g_off[node], end = g_off[node + 1];
    int i = beg;
    for (; i + 3 < end; i += 4) {
        int s0 = g_csr_src[i];
        int s1 = g_csr_src[i + 1];
        int s2 = g_csr_src[i + 2];
        int s3 = g_csr_src[i + 3];
        uint2 u0 = *reinterpret_cast<const uint2*>(&g_H2h[(size_t)s0 * OUT_FEATS + lane * 4]);
        uint2 u1 = *reinterpret_cast<const uint2*>(&g_H2h[(size_t)s1 * OUT_FEATS + lane * 4]);
        uint2 u2 = *reinterpret_cast<const uint2*>(&g_H2h[(size_t)s2 * OUT_FEATS + lane * 4]);
        uint2 u3 = *reinterpret_cast<const uint2*>(&g_H2h[(size_t)s3 * OUT_FEATS + lane * 4]);
        float w0 = g_dinv[s0] * wd;
        float w1 = g_dinv[s1] * wd;
        float w2 = g_dinv[s2] * wd;
        float w3 = g_dinv[s3] * wd;
        acc4(a, u0, w0);
        acc4(a, u1, w1);
        acc4(a, u2, w2);
        acc4(a, u3, w3);
    }
    for (; i < end; i++) {
        int s0 = g_csr_src[i];
        float w0 = g_dinv[s0] * wd;
        uint2 u0 = *reinterpret_cast<const uint2*>(&g_H2h[(size_t)s0 * OUT_FEATS + lane * 4]);
        acc4(a, u0, w0);
    }

    float4 bb = *reinterpret_cast<const float4*>(&b2[lane * 4]);
    *reinterpret_cast<float4*>(&out[(size_t)node * OUT_FEATS + lane * 4]) =
        make_float4(a[0] + bb.x, a[1] + bb.y, a[2] + bb.z, a[3] + bb.w);
}

// ------------------------------------------------------------------------
// launch: R11 structure (fork CSR ∥ GEMM1; serial layer 2)
// ------------------------------------------------------------------------
extern "C" void kernel_launch(void* const* d_in, const int* in_sizes, int n_in,
                              void* d_out, int out_size) {
    const float* x  = (const float*)d_in[0];
    const int*   ei = (const int*)d_in[1];
    const float* W1 = (const float*)d_in[2];
    const float* b1 = (const float*)d_in[3];
    const float* W2 = (const float*)d_in[4];
    const float* b2 = (const float*)d_in[5];
    float* out = (float*)d_out;

    const int* src = ei;
    const int* dst = ei + N_EDGES;

    __half *w1h, *H1h, *h1a, *w2h, *H2h;
    cudaGetSymbolAddress((void**)&w1h, g_w1h);
    cudaGetSymbolAddress((void**)&H1h, g_H1h);
    cudaGetSymbolAddress((void**)&h1a, g_h1a);
    cudaGetSymbolAddress((void**)&w2h, g_w2h);
    cudaGetSymbolAddress((void**)&H2h, g_H2h);

    static cudaStream_t s_side = nullptr;
    static cudaEvent_t ev_fork = nullptr, ev_join = nullptr;
    if (s_side == nullptr) {
        cudaStreamCreateWithFlags(&s_side, cudaStreamNonBlocking);
        cudaEventCreateWithFlags(&ev_fork, cudaEventDisableTiming);
        cudaEventCreateWithFlags(&ev_join, cudaEventDisableTiming);
        cudaFuncSetAttribute(k_mma_xA<IN_FEATS>, cudaFuncAttributeMaxDynamicSharedMemorySize, SMEMB1);
        cudaFuncSetAttribute(k_mma<HIDDEN>,      cudaFuncAttributeMaxDynamicSharedMemorySize, SMEMB2);
    }

    // fork: side stream inherits main-stream ordering
    cudaEventRecord(ev_fork, 0);
    cudaStreamWaitEvent(s_side, ev_fork, 0);

    // side branch: CSR build + W2 transpose
    k_zero_cnt<<<(N_NODES + 255) / 256, 256, 0, s_side>>>();
    k_count<<<(N_EDGES / 8 + 255) / 256, 256, 0, s_side>>>(dst);
    k_bsum<<<SCAN_NBLK, 256, 0, s_side>>>();
    k_bscan<<<1, 256, 0, s_side>>>();
    k_off<<<SCAN_NBLK, 256, 0, s_side>>>();
    k_fill<<<(N_EDGES / 8 + 255) / 256, 256, 0, s_side>>>(src, dst);
    k_wT<<<(OUT_FEATS * HIDDEN + 255) / 256, 256, 0, s_side>>>(W2, HIDDEN, OUT_FEATS, w2h);
    cudaEventRecord(ev_join, s_side);

    // main branch: W1 transpose, fused-convert GEMM1 (128x256 tiles, 512 thr)
    k_wT<<<(HIDDEN * IN_FEATS + 255) / 256, 256>>>(W1, IN_FEATS, HIDDEN, w1h);
    k_mma_xA<IN_FEATS><<<M_PAD / 128, 512, SMEMB1>>>(x, w1h, H1h, HIDDEN);

    // join: agg1 needs CSR + H1h
    cudaStreamWaitEvent(0, ev_join, 0);
    k_agg1<<<(N_NODES + 7) / 8, 256>>>(b1);

    // layer 2
    k_mma<HIDDEN><<<dim3(OUT_FEATS / 128, M_PAD / 128), 256, SMEMB2>>>(
        h1a, w2h, H2h, OUT_FEATS);
    k_agg2<<<(N_NODES + 7) / 8, 256>>>(b2, out);
}

// round 15
// speedup vs baseline: 1.0406x; 1.0143x over previous
#include <cuda_runtime.h>
#include <cuda_fp16.h>
#include <cstdint>

#define N_NODES 50000
#define M_PAD   50048
#define N_EDGES 800000
#define IN_FEATS 768
#define HIDDEN 256
#define OUT_FEATS 128
#define SCAN_NBLK ((N_NODES + 255) / 256)   // 196

// ------------------------------------------------------------------------
// device scratch
// ------------------------------------------------------------------------
__device__ int   g_cnt[N_NODES];
__device__ int   g_off[N_NODES + 1];
__device__ int   g_cur[N_NODES];
__device__ int   g_csr_src[N_EDGES];
__device__ float g_dinv[N_NODES];
__device__ int   g_bsum[SCAN_NBLK];
__device__ int   g_bpre[SCAN_NBLK];

__device__ __half g_w1h [HIDDEN * IN_FEATS];          // fp16(W1^T)
__device__ __half g_H1h [(size_t)M_PAD * HIDDEN];     // fp16(X @ W1)  pre-agg
__device__ __half g_h1a [(size_t)M_PAD * HIDDEN];     // fp16(relu(agg+b1)); pad rows stay 0
__device__ __half g_w2h [OUT_FEATS * HIDDEN];         // fp16(W2^T)
__device__ __half g_H2h [(size_t)M_PAD * OUT_FEATS];  // fp16(h1a @ W2) pre-agg

// ------------------------------------------------------------------------
// PTX helpers
// ------------------------------------------------------------------------
__device__ __forceinline__ uint32_t smem_u32(const void* p) {
    uint32_t a;
    asm("{ .reg .u64 t; cvta.to.shared.u64 t, %1; cvt.u32.u64 %0, t; }"
        : "=r"(a) : "l"(p));
    return a;
}

__device__ __forceinline__ void cp16(uint32_t dst, const void* src) {
    asm volatile("cp.async.cg.shared.global [%0], [%1], 16;" :: "r"(dst), "l"(src) : "memory");
}

__device__ __forceinline__ void ldsm_x4(uint32_t* r, uint32_t addr) {
    asm volatile("ldmatrix.sync.aligned.m8n8.x4.shared.b16 {%0,%1,%2,%3}, [%4];"
                 : "=r"(r[0]), "=r"(r[1]), "=r"(r[2]), "=r"(r[3]) : "r"(addr));
}

__device__ __forceinline__ void mma_f16(float* d, const uint32_t* a, const uint32_t* b) {
    asm volatile(
        "mma.sync.aligned.m16n8k16.row.col.f32.f16.f16.f32 "
        "{%0,%1,%2,%3}, {%4,%5,%6,%7}, {%8,%9}, {%0,%1,%2,%3};"
        : "+f"(d[0]), "+f"(d[1]), "+f"(d[2]), "+f"(d[3])
        : "r"(a[0]), "r"(a[1]), "r"(a[2]), "r"(a[3]), "r"(b[0]), "r"(b[1]));
}

// convert 8 fp32 -> 8 fp16 and store 16B to smem
__device__ __forceinline__ void cvt_sts16(uint32_t dst, const float4& lo, const float4& hi) {
    __half2 h[4];
    h[0] = __floats2half2_rn(lo.x, lo.y);
    h[1] = __floats2half2_rn(lo.z, lo.w);
    h[2] = __floats2half2_rn(hi.x, hi.y);
    h[3] = __floats2half2_rn(hi.z, hi.w);
    uint4 u = *reinterpret_cast<const uint4*>(h);
    asm volatile("st.shared.v4.b32 [%0], {%1,%2,%3,%4};"
                 :: "r"(dst), "r"(u.x), "r"(u.y), "r"(u.z), "r"(u.w) : "memory");
}

__device__ __forceinline__ void acc8(float* a, const uint4& u, float w) {
    const __half2* h = reinterpret_cast<const __half2*>(&u);
#pragma unroll
    for (int t = 0; t < 4; t++) {
        float2 f = __half22float2(h[t]);
        a[2 * t]     += f.x * w;
        a[2 * t + 1] += f.y * w;
    }
}

__device__ __forceinline__ void acc4(float* a, const uint2& u, float w) {
    const __half2* h = reinterpret_cast<const __half2*>(&u);
#pragma unroll
    for (int t = 0; t < 2; t++) {
        float2 f = __half22float2(h[t]);
        a[2 * t]     += f.x * w;
        a[2 * t + 1] += f.y * w;
    }
}

// ------------------------------------------------------------------------
// CSR build
// ------------------------------------------------------------------------
__global__ void k_zero_cnt() {
    int i = blockIdx.x * blockDim.x + threadIdx.x;
    if (i < N_NODES) g_cnt[i] = 0;
}

__global__ void k_count(const int* __restrict__ dst) {
    int e8 = (blockIdx.x * blockDim.x + threadIdx.x) * 8;
    if (e8 < N_EDGES) {
        int4 d0 = *reinterpret_cast<const int4*>(dst + e8);
        int4 d1 = *reinterpret_cast<const int4*>(dst + e8 + 4);
        atomicAdd(&g_cnt[d0.x], 1); atomicAdd(&g_cnt[d0.y], 1);
        atomicAdd(&g_cnt[d0.z], 1); atomicAdd(&g_cnt[d0.w], 1);
        atomicAdd(&g_cnt[d1.x], 1); atomicAdd(&g_cnt[d1.y], 1);
        atomicAdd(&g_cnt[d1.z], 1); atomicAdd(&g_cnt[d1.w], 1);
    }
}

__global__ void k_bsum() {
    __shared__ int s[256];
    int t = threadIdx.x;
    int i = blockIdx.x * 256 + t;
    int v = (i < N_NODES) ? g_cnt[i] : 0;
    s[t] = v;
    __syncthreads();
    for (int o = 1; o < 256; o <<= 1) {
        int u = (t >= o) ? s[t - o] : 0;
        __syncthreads();
        s[t] += u;
        __syncthreads();
    }
    if (t == 255) g_bsum[blockIdx.x] = s[255];
}

__global__ void k_bscan() {
    __shared__ int s[256];
    int t = threadIdx.x;
    int v = (t < SCAN_NBLK) ? g_bsum[t] : 0;
    s[t] = v;
    __syncthreads();
    for (int o = 1; o < 256; o <<= 1) {
        int u = (t >= o) ? s[t - o] : 0;
        __syncthreads();
        s[t] += u;
        __syncthreads();
    }
    if (t < SCAN_NBLK) g_bpre[t] = s[t] - v;
}

__global__ void k_off() {
    __shared__ int s[256];
    int t = threadIdx.x;
    int i = blockIdx.x * 256 + t;
    int v = (i < N_NODES) ? g_cnt[i] : 0;
    s[t] = v;
    __syncthreads();
    for (int o = 1; o < 256; o <<= 1) {
        int u = (t >= o) ? s[t - o] : 0;
        __syncthreads();
        s[t] += u;
        __syncthreads();
    }
    if (i < N_NODES) {
        int pre = g_bpre[blockIdx.x] + s[t] - v;
        g_off[i] = pre;
        g_cur[i] = pre;
        g_dinv[i] = rsqrtf((float)(v + 1));
    }
    if (i == 0) g_off[N_NODES] = N_EDGES;
}

__global__ void k_fill(const int* __restrict__ src, const int* __restrict__ dst) {
    int e8 = (blockIdx.x * blockDim.x + threadIdx.x) * 8;
    if (e8 < N_EDGES) {
        int4 d0 = *reinterpret_cast<const int4*>(dst + e8);
        int4 d1 = *reinterpret_cast<const int4*>(dst + e8 + 4);
        int4 s0 = *reinterpret_cast<const int4*>(src + e8);
        int4 s1 = *reinterpret_cast<const int4*>(src + e8 + 4);
        g_csr_src[atomicAdd(&g_cur[d0.x], 1)] = s0.x;
        g_csr_src[atomicAdd(&g_cur[d0.y], 1)] = s0.y;
        g_csr_src[atomicAdd(&g_cur[d0.z], 1)] = s0.z;
        g_csr_src[atomicAdd(&g_cur[d0.w], 1)] = s0.w;
        g_csr_src[atomicAdd(&g_cur[d1.x], 1)] = s1.x;
        g_csr_src[atomicAdd(&g_cur[d1.y], 1)] = s1.y;
        g_csr_src[atomicAdd(&g_cur[d1.z], 1)] = s1.z;
        g_csr_src[atomicAdd(&g_cur[d1.w], 1)] = s1.w;
    }
}

// tiled transpose + fp16 convert: W[K][N] -> out[N][K], both sides coalesced
__global__ void k_wTt(const float* __restrict__ W, int K, int N,
                      __half* __restrict__ out) {
    __shared__ float s[32][33];
    int tx = threadIdx.x;              // 0..31
    int ty = threadIdx.y;              // 0..7
    int k0 = blockIdx.y * 32, n0 = blockIdx.x * 32;
#pragma unroll
    for (int i = 0; i < 32; i += 8)
        s[ty + i][tx] = W[(size_t)(k0 + ty + i) * N + n0 + tx];
    __syncthreads();
#pragma unroll
    for (int i = 0; i < 32; i += 8)
        out[(size_t)(n0 + ty + i) * K + k0 + tx] = __float2half_rn(s[tx][ty + i]);
}

// ------------------------------------------------------------------------
// GEMM constants
// ------------------------------------------------------------------------
static constexpr int ROWB   = 80;
static constexpr int TILEB  = 128 * ROWB;            // 10240 (128-row tile)
static constexpr int TILEB2 = 256 * ROWB;            // 20480 (256-row tile)

// ==========================================================================
// GEMM1 (R11 config + hoisted A prefetch): C[M,256] = fp16(A_fp32) * B^T,
// CTA tile 128x256, 256 threads. A converted on the fly (double buffer);
// B 4-stage cp.async.  smem = 102400, 1 CTA/SM.
// ==========================================================================
static constexpr int SMEMB1 = 2 * TILEB + 4 * TILEB2;   // 102400

template <int KTOT>
__device__ __forceinline__ void load_B1(
    uint32_t sbB, int tid, int kc, const __half* __restrict__ B)
{
    const int k0 = kc * 32;
#pragma unroll
    for (int j = 0; j < 4; j++) {                   // 256 rows * 4 chunks / 256 thr
        int linear = j * 256 + tid;
        int row    = linear >> 2;
        int chunk  = linear & 3;
        cp16(sbB + row * ROWB + chunk * 16,
             B + (size_t)row * KTOT + k0 + chunk * 8);
    }
    asm volatile("cp.async.commit_group;" ::: "memory");
}

template <int KTOT>
__global__ __launch_bounds__(256, 1) void k_mma_xA(
    const float* __restrict__ A,        // fp32 [N_NODES, KTOT]
    const __half* __restrict__ B,       // fp16 [256, KTOT]
    __half* __restrict__ C, int ldc)
{
    constexpr int NC = KTOT / 32;
    extern __shared__ __align__(128) char smem[];
    const uint32_t sb0 = smem_u32(smem);            // A bufs at 0, TILEB
    const uint32_t sbB0 = sb0 + 2 * TILEB;          // B stages
    const int tid  = threadIdx.x;
    const int lane = tid & 31;
    const int wid  = tid >> 5;
    const int wm   = wid & 3;        // 4 warps down M (32 rows)
    const int wn   = wid >> 2;       // 2 warps across N (128 cols)
    const int m0 = blockIdx.x * 128;

    const int l0 = tid, l1 = 256 + tid;
    const int ar0 = l0 >> 2, ac0 = l0 & 3;
    const int ar1 = l1 >> 2, ac1 = l1 & 3;
    const bool av0 = (m0 + ar0) < N_NODES;
    const bool av1 = (m0 + ar1) < N_NODES;
    const float* ap0 = A + (size_t)(m0 + ar0) * KTOT + ac0 * 8;
    const float* ap1 = A + (size_t)(m0 + ar1) * KTOT + ac1 * 8;
    const uint32_t ao0 = ar0 * ROWB + ac0 * 16;
    const uint32_t ao1 = ar1 * ROWB + ac1 * 16;

    float acc[2][16][4];
#pragma unroll
    for (int i = 0; i < 2; i++)
#pragma unroll
        for (int j = 0; j < 16; j++)
#pragma unroll
            for (int q = 0; q < 4; q++) acc[i][j][q] = 0.f;

    const int g = lane >> 3;
    const int r = lane & 7;
    const float4 z4 = make_float4(0.f, 0.f, 0.f, 0.f);

    load_B1<KTOT>(sbB0, tid, 0, B);
    if (NC > 1) load_B1<KTOT>(sbB0 + TILEB2, tid, 1, B);
    if (NC > 2) load_B1<KTOT>(sbB0 + 2 * TILEB2, tid, 2, B);
    {
        float4 p0a = av0 ? *reinterpret_cast<const float4*>(ap0)     : z4;
        float4 p0b = av0 ? *reinterpret_cast<const float4*>(ap0 + 4) : z4;
        float4 p1a = av1 ? *reinterpret_cast<const float4*>(ap1)     : z4;
        float4 p1b = av1 ? *reinterpret_cast<const float4*>(ap1 + 4) : z4;
        cvt_sts16(sb0 + ao0, p0a, p0b);
        cvt_sts16(sb0 + ao1, p1a, p1b);
    }

    for (int c = 0; c < NC; c++) {
        // hoisted A prefetch for chunk c+1: issue LDGs before the barrier so
        // DRAM latency overlaps the cp.async drain + syncthreads
        float4 p0a = z4, p0b = z4, p1a = z4, p1b = z4;
        if (c + 1 < NC) {
            const int k0n = (c + 1) * 32;
            if (av0) {
                p0a = *reinterpret_cast<const float4*>(ap0 + k0n);
                p0b = *reinterpret_cast<const float4*>(ap0 + k0n + 4);
            }
            if (av1) {
                p1a = *reinterpret_cast<const float4*>(ap1 + k0n);
                p1b = *reinterpret_cast<const float4*>(ap1 + k0n + 4);
            }
        }

        const int rem = NC - 1 - c;
        if (rem >= 2)      asm volatile("cp.async.wait_group 2;" ::: "memory");
        else if (rem == 1) asm volatile("cp.async.wait_group 1;" ::: "memory");
        else               asm volatile("cp.async.wait_group 0;" ::: "memory");
        __syncthreads();

        if (c + 3 < NC)
            load_B1<KTOT>(sbB0 + ((c + 3) & 3) * TILEB2, tid, c + 3, B);

        const uint32_t sbA = sb0 + (c & 1) * TILEB;
        const uint32_t sbB = sbB0 + (c & 3) * TILEB2;
#pragma unroll
        for (int kk = 0; kk < 2; kk++) {
            uint32_t af[2][4];
#pragma unroll
            for (int ms = 0; ms < 2; ms++) {
                uint32_t arow = wm * 32 + ms * 16 + ((g & 1) << 3) + r;
                uint32_t aoff = arow * ROWB + kk * 32 + ((g >> 1) << 4);
                ldsm_x4(af[ms], sbA + aoff);
            }
#pragma unroll
            for (int nb2 = 0; nb2 < 8; nb2++) {
                uint32_t nrow = wn * 128 + nb2 * 16 + ((g >> 1) << 3) + r;
                uint32_t boff = nrow * ROWB + kk * 32 + ((g & 1) << 4);
                uint32_t bf[4];
                ldsm_x4(bf, sbB + boff);
#pragma unroll
                for (int ms = 0; ms < 2; ms++)
#pragma unroll
                    for (int h = 0; h < 2; h++)
                        mma_f16(acc[ms][nb2 * 2 + h], af[ms], &bf[h * 2]);
            }
        }

        if (c + 1 < NC) {
            const uint32_t sbAn = sb0 + ((c + 1) & 1) * TILEB;
            cvt_sts16(sbAn + ao0, p0a, p0b);
            cvt_sts16(sbAn + ao1, p1a, p1b);
        }
    }

#pragma unroll
    for (int ms = 0; ms < 2; ms++) {
        int grow = m0 + wm * 32 + ms * 16 + (lane >> 2);
#pragma unroll
        for (int nb = 0; nb < 16; nb++) {
            int gcol = wn * 128 + nb * 8 + (lane & 3) * 2;
            *reinterpret_cast<__half2*>(&C[(size_t)grow * ldc + gcol]) =
                __floats2half2_rn(acc[ms][nb][0], acc[ms][nb][1]);
            *reinterpret_cast<__half2*>(&C[(size_t)(grow + 8) * ldc + gcol]) =
                __floats2half2_rn(acc[ms][nb][2], acc[ms][nb][3]);
        }
    }
}

// ==========================================================================
// GEMM2: fp16 A and B via 5-stage cp.async, ONE barrier per chunk
// ==========================================================================
static constexpr int STAGEB = 2 * TILEB;
static constexpr int NSTAGE = 5;
static constexpr int SMEMB2 = NSTAGE * STAGEB;      // 102400

template <int KTOT>
__device__ __forceinline__ void load_stage(
    uint32_t sb, int tid, int kc, int m0, int n0,
    const __half* __restrict__ A, const __half* __restrict__ B)
{
    const int k0 = kc * 32;
#pragma unroll
    for (int j = 0; j < 4; j++) {
        int linear = j * 256 + tid;
        int tile   = linear >> 9;
        int within = linear & 511;
        int row    = within >> 2;
        int chunk  = within & 3;
        const __half* base = (tile == 0) ? A : B;
        int grow = ((tile == 0) ? m0 : n0) + row;
        const void* g = base + (size_t)grow * KTOT + k0 + chunk * 8;
        cp16(sb + tile * TILEB + row * ROWB + chunk * 16, g);
    }
    asm volatile("cp.async.commit_group;" ::: "memory");
}

template <int KTOT>
__global__ __launch_bounds__(256, 2) void k_mma(
    const __half* __restrict__ A, const __half* __restrict__ B,
    __half* __restrict__ C, int ldc)
{
    constexpr int NC = KTOT / 32;
    extern __shared__ __align__(128) char smem[];
    const uint32_t sb0 = smem_u32(smem);
    const int tid  = threadIdx.x;
    const int lane = tid & 31;
    const int wid  = tid >> 5;
    const int wm   = wid & 3;
    const int wn   = wid >> 2;
    const int m0 = blockIdx.y * 128, n0 = blockIdx.x * 128;

    float acc[2][8][4];
#pragma unroll
    for (int i = 0; i < 2; i++)
#pragma unroll
        for (int j = 0; j < 8; j++)
#pragma unroll
            for (int q = 0; q < 4; q++) acc[i][j][q] = 0.f;

    const int g = lane >> 3;
    const int r = lane & 7;

    load_stage<KTOT>(sb0, tid, 0, m0, n0, A, B);
    if (NC > 1) load_stage<KTOT>(sb0 + STAGEB, tid, 1, m0, n0, A, B);
    if (NC > 2) load_stage<KTOT>(sb0 + 2 * STAGEB, tid, 2, m0, n0, A, B);
    if (NC > 3) load_stage<KTOT>(sb0 + 3 * STAGEB, tid, 3, m0, n0, A, B);

    for (int c = 0; c < NC; c++) {
        const int rem = NC - 1 - c;
        if (rem >= 3)      asm volatile("cp.async.wait_group 3;" ::: "memory");
        else if (rem == 2) asm volatile("cp.async.wait_group 2;" ::: "memory");
        else if (rem == 1) asm volatile("cp.async.wait_group 1;" ::: "memory");
        else               asm volatile("cp.async.wait_group 0;" ::: "memory");
        __syncthreads();

        if (c + 4 < NC)
            load_stage<KTOT>(sb0 + ((c + 4) % NSTAGE) * STAGEB, tid, c + 4,
                             m0, n0, A, B);

        const uint32_t sb = sb0 + (c % NSTAGE) * STAGEB;
#pragma unroll
        for (int kk = 0; kk < 2; kk++) {
            uint32_t af[2][4];
#pragma unroll
            for (int ms = 0; ms < 2; ms++) {
                uint32_t arow = wm * 32 + ms * 16 + ((g & 1) << 3) + r;
                uint32_t aoff = arow * ROWB + kk * 32 + ((g >> 1) << 4);
                ldsm_x4(af[ms], sb + aoff);
            }
#pragma unroll
            for (int nb2 = 0; nb2 < 4; nb2++) {
                uint32_t nrow = wn * 64 + nb2 * 16 + ((g >> 1) << 3) + r;
                uint32_t boff = nrow * ROWB + kk * 32 + ((g & 1) << 4);
                uint32_t bf[4];
                ldsm_x4(bf, sb + TILEB + boff);
#pragma unroll
                for (int ms = 0; ms < 2; ms++)
#pragma unroll
                    for (int h = 0; h < 2; h++)
                        mma_f16(acc[ms][nb2 * 2 + h], af[ms], &bf[h * 2]);
            }
        }
    }

#pragma unroll
    for (int ms = 0; ms < 2; ms++) {
        int grow = m0 + wm * 32 + ms * 16 + (lane >> 2);
#pragma unroll
        for (int nb = 0; nb < 8; nb++) {
            int gcol = n0 + wn * 64 + nb * 8 + (lane & 3) * 2;
            *reinterpret_cast<__half2*>(&C[(size_t)grow * ldc + gcol]) =
                __floats2half2_rn(acc[ms][nb][0], acc[ms][nb][1]);
            *reinterpret_cast<__half2*>(&C[(size_t)(grow + 8) * ldc + gcol]) =
                __floats2half2_rn(acc[ms][nb][2], acc[ms][nb][3]);
        }
    }
}

// ------------------------------------------------------------------------
// aggregation: warp-per-node fp16 gather, fp32 accumulate
// ------------------------------------------------------------------------
__global__ __launch_bounds__(256) void k_agg1(const float* __restrict__ b1) {
    int node = blockIdx.x * 8 + (threadIdx.x >> 5);
    if (node >= N_NODES) return;
    int lane = threadIdx.x & 31;
    float wd = g_dinv[node];

    float a[8];
    {
        uint4 u = *reinterpret_cast<const uint4*>(&g_H1h[(size_t)node * HIDDEN + lane * 8]);
        const __half2* h = reinterpret_cast<const __half2*>(&u);
        float sw = wd * wd;
#pragma unroll
        for (int t = 0; t < 4; t++) {
            float2 f = __half22float2(h[t]);
            a[2 * t]     = f.x * sw;
            a[2 * t + 1] = f.y * sw;
        }
    }

    int beg = g_off[node], end = g_off[node + 1];
    int i = beg;
    for (; i + 3 < end; i += 4) {
        int s0 = g_csr_src[i];
        int s1 = g_csr_src[i + 1];
        int s2 = g_csr_src[i + 2];
        int s3 = g_csr_src[i + 3];
        uint4 u0 = *reinterpret_cast<const uint4*>(&g_H1h[(size_t)s0 * HIDDEN + lane * 8]);
        uint4 u1 = *reinterpret_cast<const uint4*>(&g_H1h[(size_t)s1 * HIDDEN + lane * 8]);
        uint4 u2 = *reinterpret_cast<const uint4*>(&g_H1h[(size_t)s2 * HIDDEN + lane * 8]);
        uint4 u3 = *reinterpret_cast<const uint4*>(&g_H1h[(size_t)s3 * HIDDEN + lane * 8]);
        float w0 = g_dinv[s0] * wd;
        float w1 = g_dinv[s1] * wd;
        float w2 = g_dinv[s2] * wd;
        float w3 = g_dinv[s3] * wd;
        acc8(a, u0, w0);
        acc8(a, u1, w1);
        acc8(a, u2, w2);
        acc8(a, u3, w3);
    }
    for (; i < end; i++) {
        int s0 = g_csr_src[i];
        float w0 = g_dinv[s0] * wd;
        uint4 u0 = *reinterpret_cast<const uint4*>(&g_H1h[(size_t)s0 * HIDDEN + lane * 8]);
        acc8(a, u0, w0);
    }

    float4 bb0 = *reinterpret_cast<const float4*>(&b1[lane * 8]);
    float4 bb1 = *reinterpret_cast<const float4*>(&b1[lane * 8 + 4]);
    float rr[8];
    rr[0] = fmaxf(a[0] + bb0.x, 0.f); rr[1] = fmaxf(a[1] + bb0.y, 0.f);
    rr[2] = fmaxf(a[2] + bb0.z, 0.f); rr[3] = fmaxf(a[3] + bb0.w, 0.f);
    rr[4] = fmaxf(a[4] + bb1.x, 0.f); rr[5] = fmaxf(a[5] + bb1.y, 0.f);
    rr[6] = fmaxf(a[6] + bb1.z, 0.f); rr[7] = fmaxf(a[7] + bb1.w, 0.f);

    __half2 o[4];
#pragma unroll
    for (int t = 0; t < 4; t++) o[t] = __floats2half2_rn(rr[2 * t], rr[2 * t + 1]);
    *reinterpret_cast<uint4*>(&g_h1a[(size_t)node * HIDDEN + lane * 8]) =
        *reinterpret_cast<const uint4*>(o);
}

__global__ __launch_bounds__(256) void k_agg2(const float* __restrict__ b2,
                                              float* __restrict__ out) {
    int node = blockIdx.x * 8 + (threadIdx.x >> 5);
    if (node >= N_NODES) return;
    int lane = threadIdx.x & 31;
    float wd = g_dinv[node];

    float a[4];
    {
        uint2 u = *reinterpret_cast<const uint2*>(&g_H2h[(size_t)node * OUT_FEATS + lane * 4]);
        const __half2* h = reinterpret_cast<const __half2*>(&u);
        float sw = wd * wd;
#pragma unroll
        for (int t = 0; t < 2; t++) {
            float2 f = __half22float2(h[t]);
            a[2 * t]     = f.x * sw;
            a[2 * t + 1] = f.y * sw;
        }
    }

    int beg = g_off[node], end = g_off[node + 1];
    int i = beg;
    for (; i + 3 < end; i += 4) {
        int s0 = g_csr_src[i];
        int s1 = g_csr_src[i + 1];
        int s2 = g_csr_src[i + 2];
        int s3 = g_csr_src[i + 3];
        uint2 u0 = *reinterpret_cast<const uint2*>(&g_H2h[(size_t)s0 * OUT_FEATS + lane * 4]);
        uint2 u1 = *reinterpret_cast<const uint2*>(&g_H2h[(size_t)s1 * OUT_FEATS + lane * 4]);
        uint2 u2 = *reinterpret_cast<const uint2*>(&g_H2h[(size_t)s2 * OUT_FEATS + lane * 4]);
        uint2 u3 = *reinterpret_cast<const uint2*>(&g_H2h[(size_t)s3 * OUT_FEATS + lane * 4]);
        float w0 = g_dinv[s0] * wd;
        float w1 = g_dinv[s1] * wd;
        float w2 = g_dinv[s2] * wd;
        float w3 = g_dinv[s3] * wd;
        acc4(a, u0, w0);
        acc4(a, u1, w1);
        acc4(a, u2, w2);
        acc4(a, u3, w3);
    }
    for (; i < end; i++) {
        int s0 = g_csr_src[i];
        float w0 = g_dinv[s0] * wd;
        uint2 u0 = *reinterpret_cast<const uint2*>(&g_H2h[(size_t)s0 * OUT_FEATS + lane * 4]);
        acc4(a, u0, w0);
    }

    float4 bb = *reinterpret_cast<const float4*>(&b2[lane * 4]);
    *reinterpret_cast<float4*>(&out[(size_t)node * OUT_FEATS + lane * 4]) =
        make_float4(a[0] + bb.x, a[1] + bb.y, a[2] + bb.z, a[3] + bb.w);
}

// ------------------------------------------------------------------------
// launch: R11 structure (fork CSR ∥ GEMM1; serial layer 2)
// ------------------------------------------------------------------------
extern "C" void kernel_launch(void* const* d_in, const int* in_sizes, int n_in,
                              void* d_out, int out_size) {
    const float* x  = (const float*)d_in[0];
    const int*   ei = (const int*)d_in[1];
    const float* W1 = (const float*)d_in[2];
    const float* b1 = (const float*)d_in[3];
    const float* W2 = (const float*)d_in[4];
    const float* b2 = (const float*)d_in[5];
    float* out = (float*)d_out;

    const int* src = ei;
    const int* dst = ei + N_EDGES;

    __half *w1h, *H1h, *h1a, *w2h, *H2h;
    cudaGetSymbolAddress((void**)&w1h, g_w1h);
    cudaGetSymbolAddress((void**)&H1h, g_H1h);
    cudaGetSymbolAddress((void**)&h1a, g_h1a);
    cudaGetSymbolAddress((void**)&w2h, g_w2h);
    cudaGetSymbolAddress((void**)&H2h, g_H2h);

    static cudaStream_t s_side = nullptr;
    static cudaEvent_t ev_fork = nullptr, ev_join = nullptr;
    if (s_side == nullptr) {
        cudaStreamCreateWithFlags(&s_side, cudaStreamNonBlocking);
        cudaEventCreateWithFlags(&ev_fork, cudaEventDisableTiming);
        cudaEventCreateWithFlags(&ev_join, cudaEventDisableTiming);
        cudaFuncSetAttribute(k_mma_xA<IN_FEATS>, cudaFuncAttributeMaxDynamicSharedMemorySize, SMEMB1);
        cudaFuncSetAttribute(k_mma<HIDDEN>,      cudaFuncAttributeMaxDynamicSharedMemorySize, SMEMB2);
    }

    // fork: side stream inherits main-stream ordering
    cudaEventRecord(ev_fork, 0);
    cudaStreamWaitEvent(s_side, ev_fork, 0);

    // side branch: CSR build + W2 transpose
    k_zero_cnt<<<(N_NODES + 255) / 256, 256, 0, s_side>>>();
    k_count<<<(N_EDGES / 8 + 255) / 256, 256, 0, s_side>>>(dst);
    k_bsum<<<SCAN_NBLK, 256, 0, s_side>>>();
    k_bscan<<<1, 256, 0, s_side>>>();
    k_off<<<SCAN_NBLK, 256, 0, s_side>>>();
    k_fill<<<(N_EDGES / 8 + 255) / 256, 256, 0, s_side>>>(src, dst);
    k_wTt<<<dim3(OUT_FEATS / 32, HIDDEN / 32), dim3(32, 8), 0, s_side>>>(
        W2, HIDDEN, OUT_FEATS, w2h);
    cudaEventRecord(ev_join, s_side);

    // main branch: W1 transpose (tiled), fused-convert GEMM1 (128x256 tiles)
    k_wTt<<<dim3(HIDDEN / 32, IN_FEATS / 32), dim3(32, 8)>>>(
        W1, IN_FEATS, HIDDEN, w1h);
    k_mma_xA<IN_FEATS><<<M_PAD / 128, 256, SMEMB1>>>(x, w1h, H1h, HIDDEN);

    // join: agg1 needs CSR + H1h
    cudaStreamWaitEvent(0, ev_join, 0);
    k_agg1<<<(N_NODES + 7) / 8, 256>>>(b1);

    // layer 2
    k_mma<HIDDEN><<<dim3(OUT_FEATS / 128, M_PAD / 128), 256, SMEMB2>>>(
        h1a, w2h, H2h, OUT_FEATS);
    k_agg2<<<(N_NODES + 7) / 8, 256>>>(b2, out);
}

// round 16
// speedup vs baseline: 1.0427x; 1.0020x over previous
#include <cuda_runtime.h>
#include <cuda_fp16.h>
#include <cstdint>

#define N_NODES 50000
#define M_PAD   50048
#define N_EDGES 800000
#define IN_FEATS 768
#define HIDDEN 256
#define OUT_FEATS 128
#define SCAN_NBLK ((N_NODES + 255) / 256)   // 196

// ------------------------------------------------------------------------
// device scratch
// ------------------------------------------------------------------------
__device__ int   g_cnt[N_NODES];
__device__ int   g_off[N_NODES + 1];
__device__ int   g_cur[N_NODES];
__device__ int   g_csr_src[N_EDGES];
__device__ float g_dinv[N_NODES];
__device__ int   g_bsum[SCAN_NBLK];
__device__ int   g_bpre[SCAN_NBLK];

__device__ __half g_w1h [HIDDEN * IN_FEATS];          // fp16(W1^T)
__device__ __half g_H1h [(size_t)M_PAD * HIDDEN];     // fp16(X @ W1)  pre-agg
__device__ __half g_h1a [(size_t)M_PAD * HIDDEN];     // fp16(relu(agg+b1)); pad rows stay 0
__device__ __half g_w2h [OUT_FEATS * HIDDEN];         // fp16(W2^T)
__device__ __half g_H2h [(size_t)M_PAD * OUT_FEATS];  // fp16(h1a @ W2) pre-agg

// ------------------------------------------------------------------------
// PTX helpers
// ------------------------------------------------------------------------
__device__ __forceinline__ uint32_t smem_u32(const void* p) {
    uint32_t a;
    asm("{ .reg .u64 t; cvta.to.shared.u64 t, %1; cvt.u32.u64 %0, t; }"
        : "=r"(a) : "l"(p));
    return a;
}

__device__ __forceinline__ void cp16(uint32_t dst, const void* src) {
    asm volatile("cp.async.cg.shared.global [%0], [%1], 16;" :: "r"(dst), "l"(src) : "memory");
}

__device__ __forceinline__ void ldsm_x4(uint32_t* r, uint32_t addr) {
    asm volatile("ldmatrix.sync.aligned.m8n8.x4.shared.b16 {%0,%1,%2,%3}, [%4];"
                 : "=r"(r[0]), "=r"(r[1]), "=r"(r[2]), "=r"(r[3]) : "r"(addr));
}

__device__ __forceinline__ void mma_f16(float* d, const uint32_t* a, const uint32_t* b) {
    asm volatile(
        "mma.sync.aligned.m16n8k16.row.col.f32.f16.f16.f32 "
        "{%0,%1,%2,%3}, {%4,%5,%6,%7}, {%8,%9}, {%0,%1,%2,%3};"
        : "+f"(d[0]), "+f"(d[1]), "+f"(d[2]), "+f"(d[3])
        : "r"(a[0]), "r"(a[1]), "r"(a[2]), "r"(a[3]), "r"(b[0]), "r"(b[1]));
}

// convert 8 fp32 -> 8 fp16 and store 16B to smem
__device__ __forceinline__ void cvt_sts16(uint32_t dst, const float4& lo, const float4& hi) {
    __half2 h[4];
    h[0] = __floats2half2_rn(lo.x, lo.y);
    h[1] = __floats2half2_rn(lo.z, lo.w);
    h[2] = __floats2half2_rn(hi.x, hi.y);
    h[3] = __floats2half2_rn(hi.z, hi.w);
    uint4 u = *reinterpret_cast<const uint4*>(h);
    asm volatile("st.shared.v4.b32 [%0], {%1,%2,%3,%4};"
                 :: "r"(dst), "r"(u.x), "r"(u.y), "r"(u.z), "r"(u.w) : "memory");
}

__device__ __forceinline__ void acc8(float* a, const uint4& u, float w) {
    const __half2* h = reinterpret_cast<const __half2*>(&u);
#pragma unroll
    for (int t = 0; t < 4; t++) {
        float2 f = __half22float2(h[t]);
        a[2 * t]     += f.x * w;
        a[2 * t + 1] += f.y * w;
    }
}

__device__ __forceinline__ void acc4(float* a, const uint2& u, float w) {
    const __half2* h = reinterpret_cast<const __half2*>(&u);
#pragma unroll
    for (int t = 0; t < 2; t++) {
        float2 f = __half22float2(h[t]);
        a[2 * t]     += f.x * w;
        a[2 * t + 1] += f.y * w;
    }
}

// ------------------------------------------------------------------------
// CSR build
// ------------------------------------------------------------------------
__global__ void k_zero_cnt() {
    int i = blockIdx.x * blockDim.x + threadIdx.x;
    if (i < N_NODES) g_cnt[i] = 0;
}

__global__ void k_count(const int* __restrict__ dst) {
    int e8 = (blockIdx.x * blockDim.x + threadIdx.x) * 8;
    if (e8 < N_EDGES) {
        int4 d0 = *reinterpret_cast<const int4*>(dst + e8);
        int4 d1 = *reinterpret_cast<const int4*>(dst + e8 + 4);
        atomicAdd(&g_cnt[d0.x], 1); atomicAdd(&g_cnt[d0.y], 1);
        atomicAdd(&g_cnt[d0.z], 1); atomicAdd(&g_cnt[d0.w], 1);
        atomicAdd(&g_cnt[d1.x], 1); atomicAdd(&g_cnt[d1.y], 1);
        atomicAdd(&g_cnt[d1.z], 1); atomicAdd(&g_cnt[d1.w], 1);
    }
}

__global__ void k_bsum() {
    __shared__ int s[256];
    int t = threadIdx.x;
    int i = blockIdx.x * 256 + t;
    int v = (i < N_NODES) ? g_cnt[i] : 0;
    s[t] = v;
    __syncthreads();
    for (int o = 1; o < 256; o <<= 1) {
        int u = (t >= o) ? s[t - o] : 0;
        __syncthreads();
        s[t] += u;
        __syncthreads();
    }
    if (t == 255) g_bsum[blockIdx.x] = s[255];
}

__global__ void k_bscan() {
    __shared__ int s[256];
    int t = threadIdx.x;
    int v = (t < SCAN_NBLK) ? g_bsum[t] : 0;
    s[t] = v;
    __syncthreads();
    for (int o = 1; o < 256; o <<= 1) {
        int u = (t >= o) ? s[t - o] : 0;
        __syncthreads();
        s[t] += u;
        __syncthreads();
    }
    if (t < SCAN_NBLK) g_bpre[t] = s[t] - v;
}

__global__ void k_off() {
    __shared__ int s[256];
    int t = threadIdx.x;
    int i = blockIdx.x * 256 + t;
    int v = (i < N_NODES) ? g_cnt[i] : 0;
    s[t] = v;
    __syncthreads();
    for (int o = 1; o < 256; o <<= 1) {
        int u = (t >= o) ? s[t - o] : 0;
        __syncthreads();
        s[t] += u;
        __syncthreads();
    }
    if (i < N_NODES) {
        int pre = g_bpre[blockIdx.x] + s[t] - v;
        g_off[i] = pre;
        g_cur[i] = pre;
        g_dinv[i] = rsqrtf((float)(v + 1));
    }
    if (i == 0) g_off[N_NODES] = N_EDGES;
}

__global__ void k_fill(const int* __restrict__ src, const int* __restrict__ dst) {
    int e8 = (blockIdx.x * blockDim.x + threadIdx.x) * 8;
    if (e8 < N_EDGES) {
        int4 d0 = *reinterpret_cast<const int4*>(dst + e8);
        int4 d1 = *reinterpret_cast<const int4*>(dst + e8 + 4);
        int4 s0 = *reinterpret_cast<const int4*>(src + e8);
        int4 s1 = *reinterpret_cast<const int4*>(src + e8 + 4);
        g_csr_src[atomicAdd(&g_cur[d0.x], 1)] = s0.x;
        g_csr_src[atomicAdd(&g_cur[d0.y], 1)] = s0.y;
        g_csr_src[atomicAdd(&g_cur[d0.z], 1)] = s0.z;
        g_csr_src[atomicAdd(&g_cur[d0.w], 1)] = s0.w;
        g_csr_src[atomicAdd(&g_cur[d1.x], 1)] = s1.x;
        g_csr_src[atomicAdd(&g_cur[d1.y], 1)] = s1.y;
        g_csr_src[atomicAdd(&g_cur[d1.z], 1)] = s1.z;
        g_csr_src[atomicAdd(&g_cur[d1.w], 1)] = s1.w;
    }
}

// tiled transpose + fp16 convert: W[K][N] -> out[N][K], both sides coalesced
__global__ void k_wTt(const float* __restrict__ W, int K, int N,
                      __half* __restrict__ out) {
    __shared__ float s[32][33];
    int tx = threadIdx.x;
    int ty = threadIdx.y;
    int k0 = blockIdx.y * 32, n0 = blockIdx.x * 32;
#pragma unroll
    for (int i = 0; i < 32; i += 8)
        s[ty + i][tx] = W[(size_t)(k0 + ty + i) * N + n0 + tx];
    __syncthreads();
#pragma unroll
    for (int i = 0; i < 32; i += 8)
        out[(size_t)(n0 + ty + i) * K + k0 + tx] = __float2half_rn(s[tx][ty + i]);
}

// ------------------------------------------------------------------------
// GEMM constants
// ------------------------------------------------------------------------
static constexpr int ROWB   = 80;
static constexpr int TILEB  = 128 * ROWB;            // 10240 (128-row tile)
static constexpr int TILEB2 = 256 * ROWB;            // 20480 (256-row tile)

// ==========================================================================
// GEMM1: C[M,256] = fp16(A_fp32) * B^T, CTA tile 128x256, 256 threads.
// A converted on the fly (double buffer); B 4-stage cp.async.
// Inner loop: A fragments batched up-front, B fragment double-buffered
// (ldsm for step i+1 issued before step i's MMAs).
// ==========================================================================
static constexpr int SMEMB1 = 2 * TILEB + 4 * TILEB2;   // 102400

template <int KTOT>
__device__ __forceinline__ void load_B1(
    uint32_t sbB, int tid, int kc, const __half* __restrict__ B)
{
    const int k0 = kc * 32;
#pragma unroll
    for (int j = 0; j < 4; j++) {
        int linear = j * 256 + tid;
        int row    = linear >> 2;
        int chunk  = linear & 3;
        cp16(sbB + row * ROWB + chunk * 16,
             B + (size_t)row * KTOT + k0 + chunk * 8);
    }
    asm volatile("cp.async.commit_group;" ::: "memory");
}

template <int KTOT>
__global__ __launch_bounds__(256, 1) void k_mma_xA(
    const float* __restrict__ A,        // fp32 [N_NODES, KTOT]
    const __half* __restrict__ B,       // fp16 [256, KTOT]
    __half* __restrict__ C, int ldc)
{
    constexpr int NC = KTOT / 32;
    extern __shared__ __align__(128) char smem[];
    const uint32_t sb0 = smem_u32(smem);
    const uint32_t sbB0 = sb0 + 2 * TILEB;
    const int tid  = threadIdx.x;
    const int lane = tid & 31;
    const int wid  = tid >> 5;
    const int wm   = wid & 3;
    const int wn   = wid >> 2;
    const int m0 = blockIdx.x * 128;

    const int l0 = tid, l1 = 256 + tid;
    const int ar0 = l0 >> 2, ac0 = l0 & 3;
    const int ar1 = l1 >> 2, ac1 = l1 & 3;
    const bool av0 = (m0 + ar0) < N_NODES;
    const bool av1 = (m0 + ar1) < N_NODES;
    const float* ap0 = A + (size_t)(m0 + ar0) * KTOT + ac0 * 8;
    const float* ap1 = A + (size_t)(m0 + ar1) * KTOT + ac1 * 8;
    const uint32_t ao0 = ar0 * ROWB + ac0 * 16;
    const uint32_t ao1 = ar1 * ROWB + ac1 * 16;

    float acc[2][16][4];
#pragma unroll
    for (int i = 0; i < 2; i++)
#pragma unroll
        for (int j = 0; j < 16; j++)
#pragma unroll
            for (int q = 0; q < 4; q++) acc[i][j][q] = 0.f;

    const int g = lane >> 3;
    const int r = lane & 7;
    const float4 z4 = make_float4(0.f, 0.f, 0.f, 0.f);

    load_B1<KTOT>(sbB0, tid, 0, B);
    if (NC > 1) load_B1<KTOT>(sbB0 + TILEB2, tid, 1, B);
    if (NC > 2) load_B1<KTOT>(sbB0 + 2 * TILEB2, tid, 2, B);
    {
        float4 p0a = av0 ? *reinterpret_cast<const float4*>(ap0)     : z4;
        float4 p0b = av0 ? *reinterpret_cast<const float4*>(ap0 + 4) : z4;
        float4 p1a = av1 ? *reinterpret_cast<const float4*>(ap1)     : z4;
        float4 p1b = av1 ? *reinterpret_cast<const float4*>(ap1 + 4) : z4;
        cvt_sts16(sb0 + ao0, p0a, p0b);
        cvt_sts16(sb0 + ao1, p1a, p1b);
    }

    // fragment address helpers
    const uint32_t arow_base = wm * 32 + ((g & 1) << 3) + r;   // +ms*16
    const uint32_t acol_off  = (g >> 1) << 4;                  // +kk*32
    const uint32_t nrow_base = wn * 128 + ((g >> 1) << 3) + r; // +nb2*16
    const uint32_t bcol_off  = (g & 1) << 4;                   // +kk*32

    for (int c = 0; c < NC; c++) {
        float4 p0a = z4, p0b = z4, p1a = z4, p1b = z4;
        if (c + 1 < NC) {
            const int k0n = (c + 1) * 32;
            if (av0) {
                p0a = *reinterpret_cast<const float4*>(ap0 + k0n);
                p0b = *reinterpret_cast<const float4*>(ap0 + k0n + 4);
            }
            if (av1) {
                p1a = *reinterpret_cast<const float4*>(ap1 + k0n);
                p1b = *reinterpret_cast<const float4*>(ap1 + k0n + 4);
            }
        }

        const int rem = NC - 1 - c;
        if (rem >= 2)      asm volatile("cp.async.wait_group 2;" ::: "memory");
        else if (rem == 1) asm volatile("cp.async.wait_group 1;" ::: "memory");
        else               asm volatile("cp.async.wait_group 0;" ::: "memory");
        __syncthreads();

        if (c + 3 < NC)
            load_B1<KTOT>(sbB0 + ((c + 3) & 3) * TILEB2, tid, c + 3, B);

        const uint32_t sbA = sb0 + (c & 1) * TILEB;
        const uint32_t sbB = sbB0 + (c & 3) * TILEB2;

        // batch all 4 A fragments (kk x ms) up front — independent ldsm
        uint32_t af[2][2][4];
#pragma unroll
        for (int kk = 0; kk < 2; kk++)
#pragma unroll
            for (int ms = 0; ms < 2; ms++)
                ldsm_x4(af[kk][ms],
                        sbA + (arow_base + ms * 16) * ROWB + kk * 32 + acol_off);

        // B fragment double buffer over flattened (kk, nb2) steps
        uint32_t bf[2][4];
        ldsm_x4(bf[0], sbB + nrow_base * ROWB + bcol_off);   // it=0: kk=0,nb2=0
        int buf = 0;
#pragma unroll
        for (int it = 0; it < 16; it++) {
            const int kk  = it >> 3;
            const int nb2 = it & 7;
            if (it < 15) {
                const int itn  = it + 1;
                const int kkn  = itn >> 3;
                const int nb2n = itn & 7;
                ldsm_x4(bf[buf ^ 1],
                        sbB + (nrow_base + nb2n * 16) * ROWB + kkn * 32 + bcol_off);
            }
#pragma unroll
            for (int ms = 0; ms < 2; ms++)
#pragma unroll
                for (int h = 0; h < 2; h++)
                    mma_f16(acc[ms][nb2 * 2 + h], af[kk][ms], &bf[buf][h * 2]);
            buf ^= 1;
        }

        if (c + 1 < NC) {
            const uint32_t sbAn = sb0 + ((c + 1) & 1) * TILEB;
            cvt_sts16(sbAn + ao0, p0a, p0b);
            cvt_sts16(sbAn + ao1, p1a, p1b);
        }
    }

#pragma unroll
    for (int ms = 0; ms < 2; ms++) {
        int grow = m0 + wm * 32 + ms * 16 + (lane >> 2);
#pragma unroll
        for (int nb = 0; nb < 16; nb++) {
            int gcol = wn * 128 + nb * 8 + (lane & 3) * 2;
            *reinterpret_cast<__half2*>(&C[(size_t)grow * ldc + gcol]) =
                __floats2half2_rn(acc[ms][nb][0], acc[ms][nb][1]);
            *reinterpret_cast<__half2*>(&C[(size_t)(grow + 8) * ldc + gcol]) =
                __floats2half2_rn(acc[ms][nb][2], acc[ms][nb][3]);
        }
    }
}

// ==========================================================================
// GEMM2: fp16 A and B via 5-stage cp.async, one barrier per chunk
// ==========================================================================
static constexpr int STAGEB = 2 * TILEB;
static constexpr int NSTAGE = 5;
static constexpr int SMEMB2 = NSTAGE * STAGEB;      // 102400

template <int KTOT>
__device__ __forceinline__ void load_stage(
    uint32_t sb, int tid, int kc, int m0, int n0,
    const __half* __restrict__ A, const __half* __restrict__ B)
{
    const int k0 = kc * 32;
#pragma unroll
    for (int j = 0; j < 4; j++) {
        int linear = j * 256 + tid;
        int tile   = linear >> 9;
        int within = linear & 511;
        int row    = within >> 2;
        int chunk  = within & 3;
        const __half* base = (tile == 0) ? A : B;
        int grow = ((tile == 0) ? m0 : n0) + row;
        const void* g = base + (size_t)grow * KTOT + k0 + chunk * 8;
        cp16(sb + tile * TILEB + row * ROWB + chunk * 16, g);
    }
    asm volatile("cp.async.commit_group;" ::: "memory");
}

template <int KTOT>
__global__ __launch_bounds__(256, 2) void k_mma(
    const __half* __restrict__ A, const __half* __restrict__ B,
    __half* __restrict__ C, int ldc)
{
    constexpr int NC = KTOT / 32;
    extern __shared__ __align__(128) char smem[];
    const uint32_t sb0 = smem_u32(smem);
    const int tid  = threadIdx.x;
    const int lane = tid & 31;
    const int wid  = tid >> 5;
    const int wm   = wid & 3;
    const int wn   = wid >> 2;
    const int m0 = blockIdx.y * 128, n0 = blockIdx.x * 128;

    float acc[2][8][4];
#pragma unroll
    for (int i = 0; i < 2; i++)
#pragma unroll
        for (int j = 0; j < 8; j++)
#pragma unroll
            for (int q = 0; q < 4; q++) acc[i][j][q] = 0.f;

    const int g = lane >> 3;
    const int r = lane & 7;

    load_stage<KTOT>(sb0, tid, 0, m0, n0, A, B);
    if (NC > 1) load_stage<KTOT>(sb0 + STAGEB, tid, 1, m0, n0, A, B);
    if (NC > 2) load_stage<KTOT>(sb0 + 2 * STAGEB, tid, 2, m0, n0, A, B);
    if (NC > 3) load_stage<KTOT>(sb0 + 3 * STAGEB, tid, 3, m0, n0, A, B);

    for (int c = 0; c < NC; c++) {
        const int rem = NC - 1 - c;
        if (rem >= 3)      asm volatile("cp.async.wait_group 3;" ::: "memory");
        else if (rem == 2) asm volatile("cp.async.wait_group 2;" ::: "memory");
        else if (rem == 1) asm volatile("cp.async.wait_group 1;" ::: "memory");
        else               asm volatile("cp.async.wait_group 0;" ::: "memory");
        __syncthreads();

        if (c + 4 < NC)
            load_stage<KTOT>(sb0 + ((c + 4) % NSTAGE) * STAGEB, tid, c + 4,
                             m0, n0, A, B);

        const uint32_t sb = sb0 + (c % NSTAGE) * STAGEB;
#pragma unroll
        for (int kk = 0; kk < 2; kk++) {
            uint32_t af[2][4];
#pragma unroll
            for (int ms = 0; ms < 2; ms++) {
                uint32_t arow = wm * 32 + ms * 16 + ((g & 1) << 3) + r;
                uint32_t aoff = arow * ROWB + kk * 32 + ((g >> 1) << 4);
                ldsm_x4(af[ms], sb + aoff);
            }
#pragma unroll
            for (int nb2 = 0; nb2 < 4; nb2++) {
                uint32_t nrow = wn * 64 + nb2 * 16 + ((g >> 1) << 3) + r;
                uint32_t boff = nrow * ROWB + kk * 32 + ((g & 1) << 4);
                uint32_t bf[4];
                ldsm_x4(bf, sb + TILEB + boff);
#pragma unroll
                for (int ms = 0; ms < 2; ms++)
#pragma unroll
                    for (int h = 0; h < 2; h++)
                        mma_f16(acc[ms][nb2 * 2 + h], af[ms], &bf[h * 2]);
            }
        }
    }

#pragma unroll
    for (int ms = 0; ms < 2; ms++) {
        int grow = m0 + wm * 32 + ms * 16 + (lane >> 2);
#pragma unroll
        for (int nb = 0; nb < 8; nb++) {
            int gcol = n0 + wn * 64 + nb * 8 + (lane & 3) * 2;
            *reinterpret_cast<__half2*>(&C[(size_t)grow * ldc + gcol]) =
                __floats2half2_rn(acc[ms][nb][0], acc[ms][nb][1]);
            *reinterpret_cast<__half2*>(&C[(size_t)(grow + 8) * ldc + gcol]) =
                __floats2half2_rn(acc[ms][nb][2], acc[ms][nb][3]);
        }
    }
}

// ------------------------------------------------------------------------
// aggregation: warp-per-node fp16 gather, fp32 accumulate
// ------------------------------------------------------------------------
__global__ __launch_bounds__(256) void k_agg1(const float* __restrict__ b1) {
    int node = blockIdx.x * 8 + (threadIdx.x >> 5);
    if (node >= N_NODES) return;
    int lane = threadIdx.x & 31;
    float wd = g_dinv[node];

    float a[8];
    {
        uint4 u = *reinterpret_cast<const uint4*>(&g_H1h[(size_t)node * HIDDEN + lane * 8]);
        const __half2* h = reinterpret_cast<const __half2*>(&u);
        float sw = wd * wd;
#pragma unroll
        for (int t = 0; t < 4; t++) {
            float2 f = __half22float2(h[t]);
            a[2 * t]     = f.x * sw;
            a[2 * t + 1] = f.y * sw;
        }
    }

    int beg = g_off[node], end = g_off[node + 1];
    int i = beg;
    for (; i + 3 < end; i += 4) {
        int s0 = g_csr_src[i];
        int s1 = g_csr_src[i + 1];
        int s2 = g_csr_src[i + 2];
        int s3 = g_csr_src[i + 3];
        uint4 u0 = *reinterpret_cast<const uint4*>(&g_H1h[(size_t)s0 * HIDDEN + lane * 8]);
        uint4 u1 = *reinterpret_cast<const uint4*>(&g_H1h[(size_t)s1 * HIDDEN + lane * 8]);
        uint4 u2 = *reinterpret_cast<const uint4*>(&g_H1h[(size_t)s2 * HIDDEN + lane * 8]);
        uint4 u3 = *reinterpret_cast<const uint4*>(&g_H1h[(size_t)s3 * HIDDEN + lane * 8]);
        float w0 = g_dinv[s0] * wd;
        float w1 = g_dinv[s1] * wd;
        float w2 = g_dinv[s2] * wd;
        float w3 = g_dinv[s3] * wd;
        acc8(a, u0, w0);
        acc8(a, u1, w1);
        acc8(a, u2, w2);
        acc8(a, u3, w3);
    }
    for (; i < end; i++) {
        int s0 = g_csr_src[i];
        float w0 = g_dinv[s0] * wd;
        uint4 u0 = *reinterpret_cast<const uint4*>(&g_H1h[(size_t)s0 * HIDDEN + lane * 8]);
        acc8(a, u0, w0);
    }

    float4 bb0 = *reinterpret_cast<const float4*>(&b1[lane * 8]);
    float4 bb1 = *reinterpret_cast<const float4*>(&b1[lane * 8 + 4]);
    float rr[8];
    rr[0] = fmaxf(a[0] + bb0.x, 0.f); rr[1] = fmaxf(a[1] + bb0.y, 0.f);
    rr[2] = fmaxf(a[2] + bb0.z, 0.f); rr[3] = fmaxf(a[3] + bb0.w, 0.f);
    rr[4] = fmaxf(a[4] + bb1.x, 0.f); rr[5] = fmaxf(a[5] + bb1.y, 0.f);
    rr[6] = fmaxf(a[6] + bb1.z, 0.f); rr[7] = fmaxf(a[7] + bb1.w, 0.f);

    __half2 o[4];
#pragma unroll
    for (int t = 0; t < 4; t++) o[t] = __floats2half2_rn(rr[2 * t], rr[2 * t + 1]);
    *reinterpret_cast<uint4*>(&g_h1a[(size_t)node * HIDDEN + lane * 8]) =
        *reinterpret_cast<const uint4*>(o);
}

__global__ __launch_bounds__(256) void k_agg2(const float* __restrict__ b2,
                                              float* __restrict__ out) {
    int node = blockIdx.x * 8 + (threadIdx.x >> 5);
    if (node >= N_NODES) return;
    int lane = threadIdx.x & 31;
    float wd = g_dinv[node];

    float a[4];
    {
        uint2 u = *reinterpret_cast<const uint2*>(&g_H2h[(size_t)node * OUT_FEATS + lane * 4]);
        const __half2* h = reinterpret_cast<const __half2*>(&u);
        float sw = wd * wd;
#pragma unroll
        for (int t = 0; t < 2; t++) {
            float2 f = __half22float2(h[t]);
            a[2 * t]     = f.x * sw;
            a[2 * t + 1] = f.y * sw;
        }
    }

    int beg = g_off[node], end = g_off[node + 1];
    int i = beg;
    for (; i + 3 < end; i += 4) {
        int s0 = g_csr_src[i];
        int s1 = g_csr_src[i + 1];
        int s2 = g_csr_src[i + 2];
        int s3 = g_csr_src[i + 3];
        uint2 u0 = *reinterpret_cast<const uint2*>(&g_H2h[(size_t)s0 * OUT_FEATS + lane * 4]);
        uint2 u1 = *reinterpret_cast<const uint2*>(&g_H2h[(size_t)s1 * OUT_FEATS + lane * 4]);
        uint2 u2 = *reinterpret_cast<const uint2*>(&g_H2h[(size_t)s2 * OUT_FEATS + lane * 4]);
        uint2 u3 = *reinterpret_cast<const uint2*>(&g_H2h[(size_t)s3 * OUT_FEATS + lane * 4]);
        float w0 = g_dinv[s0] * wd;
        float w1 = g_dinv[s1] * wd;
        float w2 = g_dinv[s2] * wd;
        float w3 = g_dinv[s3] * wd;
        acc4(a, u0, w0);
        acc4(a, u1, w1);
        acc4(a, u2, w2);
        acc4(a, u3, w3);
    }
    for (; i < end; i++) {
        int s0 = g_csr_src[i];
        float w0 = g_dinv[s0] * wd;
        uint2 u0 = *reinterpret_cast<const uint2*>(&g_H2h[(size_t)s0 * OUT_FEATS + lane * 4]);
        acc4(a, u0, w0);
    }

    float4 bb = *reinterpret_cast<const float4*>(&b2[lane * 4]);
    *reinterpret_cast<float4*>(&out[(size_t)node * OUT_FEATS + lane * 4]) =
        make_float4(a[0] + bb.x, a[1] + bb.y, a[2] + bb.z, a[3] + bb.w);
}

// ------------------------------------------------------------------------
// launch: fork CSR ∥ GEMM1; serial layer 2
// ------------------------------------------------------------------------
extern "C" void kernel_launch(void* const* d_in, const int* in_sizes, int n_in,
                              void* d_out, int out_size) {
    const float* x  = (const float*)d_in[0];
    const int*   ei = (const int*)d_in[1];
    const float* W1 = (const float*)d_in[2];
    const float* b1 = (const float*)d_in[3];
    const float* W2 = (const float*)d_in[4];
    const float* b2 = (const float*)d_in[5];
    float* out = (float*)d_out;

    const int* src = ei;
    const int* dst = ei + N_EDGES;

    __half *w1h, *H1h, *h1a, *w2h, *H2h;
    cudaGetSymbolAddress((void**)&w1h, g_w1h);
    cudaGetSymbolAddress((void**)&H1h, g_H1h);
    cudaGetSymbolAddress((void**)&h1a, g_h1a);
    cudaGetSymbolAddress((void**)&w2h, g_w2h);
    cudaGetSymbolAddress((void**)&H2h, g_H2h);

    static cudaStream_t s_side = nullptr;
    static cudaEvent_t ev_fork = nullptr, ev_join = nullptr;
    if (s_side == nullptr) {
        cudaStreamCreateWithFlags(&s_side, cudaStreamNonBlocking);
        cudaEventCreateWithFlags(&ev_fork, cudaEventDisableTiming);
        cudaEventCreateWithFlags(&ev_join, cudaEventDisableTiming);
        cudaFuncSetAttribute(k_mma_xA<IN_FEATS>, cudaFuncAttributeMaxDynamicSharedMemorySize, SMEMB1);
        cudaFuncSetAttribute(k_mma<HIDDEN>,      cudaFuncAttributeMaxDynamicSharedMemorySize, SMEMB2);
    }

    // fork: side stream inherits main-stream ordering
    cudaEventRecord(ev_fork, 0);
    cudaStreamWaitEvent(s_side, ev_fork, 0);

    // side branch: CSR build + W2 transpose
    k_zero_cnt<<<(N_NODES + 255) / 256, 256, 0, s_side>>>();
    k_count<<<(N_EDGES / 8 + 255) / 256, 256, 0, s_side>>>(dst);
    k_bsum<<<SCAN_NBLK, 256, 0, s_side>>>();
    k_bscan<<<1, 256, 0, s_side>>>();
    k_off<<<SCAN_NBLK, 256, 0, s_side>>>();
    k_fill<<<(N_EDGES / 8 + 255) / 256, 256, 0, s_side>>>(src, dst);
    k_wTt<<<dim3(OUT_FEATS / 32, HIDDEN / 32), dim3(32, 8), 0, s_side>>>(
        W2, HIDDEN, OUT_FEATS, w2h);
    cudaEventRecord(ev_join, s_side);

    // main branch: W1 transpose (tiled), fused-convert GEMM1
    k_wTt<<<dim3(HIDDEN / 32, IN_FEATS / 32), dim3(32, 8)>>>(
        W1, IN_FEATS, HIDDEN, w1h);
    k_mma_xA<IN_FEATS><<<M_PAD / 128, 256, SMEMB1>>>(x, w1h, H1h, HIDDEN);

    // join: agg1 needs CSR + H1h
    cudaStreamWaitEvent(0, ev_join, 0);
    k_agg1<<<(N_NODES + 7) / 8, 256>>>(b1);

    // layer 2
    k_mma<HIDDEN><<<dim3(OUT_FEATS / 128, M_PAD / 128), 256, SMEMB2>>>(
        h1a, w2h, H2h, OUT_FEATS);
    k_agg2<<<(N_NODES + 7) / 8, 256>>>(b2, out);
}